// round 2
// baseline (speedup 1.0000x reference)
#include <cuda_runtime.h>

#define N_NODES_MAX 50000
#define E_MAX       800000
#define F_IN  128
#define F_HID 128
#define F_OUT 64

typedef unsigned long long ull;

// ---------------- scratch (device globals; no allocation allowed) ----------
__device__ float g_deg [N_NODES_MAX];
__device__ float g_dinv[N_NODES_MAX];
__device__ int2  g_edge[E_MAX];
__device__ float g_norm[E_MAX];
__device__ float g_h   [(size_t)N_NODES_MAX * F_IN];   // x @ W1
__device__ float g_out1[(size_t)N_NODES_MAX * F_HID];  // aggregated layer-1 (pre-bias/relu)
__device__ float g_t   [(size_t)N_NODES_MAX * F_OUT];  // relu(h1) @ W2
__device__ int   g_is64;

// ---------------- helpers --------------------------------------------------
__device__ __forceinline__ void red_add_v4(float* addr, float4 v) {
    asm volatile("red.global.add.v4.f32 [%0], {%1,%2,%3,%4};"
                 :: "l"(addr), "f"(v.x), "f"(v.y), "f"(v.z), "f"(v.w)
                 : "memory");
}

__device__ __forceinline__ void ffma2(ull& d, ull a, ull b) {
    asm("fma.rn.f32x2 %0, %1, %2, %3;" : "=l"(d) : "l"(a), "l"(b), "l"(d));
}

__device__ __forceinline__ ull dup2(float w) {
    ull r;
    asm("mov.b64 %0, {%1, %1};" : "=l"(r) : "f"(w));
    return r;
}

__device__ __forceinline__ void unpack2(float& lo, float& hi, ull v) {
    asm("mov.b64 {%0, %1}, %2;" : "=f"(lo), "=f"(hi) : "l"(v));
}

__device__ __forceinline__ int load_edge_idx(const void* ei, size_t pos) {
    if (g_is64) return (int)((const long long*)ei)[pos];
    return ((const int*)ei)[pos];
}

// ---------------- prep0: deg init + dtype detect ---------------------------
__global__ void k_prep0(const int* __restrict__ ei32, int n) {
    int i = blockIdx.x * blockDim.x + threadIdx.x;
    if (i < n) g_deg[i] = 1.0f;       // self-loop weight
    if (blockIdx.x == 0 && threadIdx.x < 32) {
        // int64 little-endian values in [0,50000): odd 32-bit words all zero
        int v = ei32[threadIdx.x * 2 + 1] | ei32[64 + threadIdx.x * 2 + 1];
        unsigned m = __ballot_sync(0xffffffffu, v != 0);
        if (threadIdx.x == 0) g_is64 = (m == 0u);
    }
}

__global__ void k_accum_deg(const void* __restrict__ ei,
                            const float* __restrict__ ew, int e) {
    int i = blockIdx.x * blockDim.x + threadIdx.x;
    if (i < e) {
        int c = load_edge_idx(ei, (size_t)e + i);
        atomicAdd(&g_deg[c], ew[i]);
    }
}

__global__ void k_dinv(int n) {
    int i = blockIdx.x * blockDim.x + threadIdx.x;
    if (i < n) {
        float d = g_deg[i];
        g_dinv[i] = (d > 0.f) ? rsqrtf(d) : 0.f;
    }
}

__global__ void k_edge_prep(const void* __restrict__ ei,
                            const float* __restrict__ ew, int e) {
    int i = blockIdx.x * blockDim.x + threadIdx.x;
    if (i < e) {
        int r = load_edge_idx(ei, (size_t)i);
        int c = load_edge_idx(ei, (size_t)e + i);
        g_edge[i] = make_int2(r, c);
        g_norm[i] = g_dinv[r] * ew[i] * g_dinv[c];
    }
}

// ---------------- GEMM1: h = x @ W1 ; out1 = h * dinv^2 (self loop) --------
// 128x128 tile, 256 threads, thread = 8 rows x 8 cols via f32x2 (row pairs).
#define XS_STRIDE 132
__global__ __launch_bounds__(256, 2) void k_gemm1(const float* __restrict__ x,
                                                  const float* __restrict__ W1,
                                                  int M) {
    __shared__ float Xs[16 * XS_STRIDE];   // [k][row], transposed, 8448 B
    __shared__ ull   Ws2[16 * 128];        // [k][col], dup {w,w}, 16 KB

    const int t = threadIdx.x;
    const int tidx = t & 15;               // col group: cols tidx*8 .. +7
    const int tidy = t >> 4;               // row group: rows tidy*8 .. +7
    const int rowbase = blockIdx.x * 128;

    ull acc[4][8];
#pragma unroll
    for (int r = 0; r < 4; r++)
#pragma unroll
        for (int c = 0; c < 8; c++) acc[r][c] = 0ull;

    for (int kb = 0; kb < 128; kb += 16) {
        // load X slice [128 rows x 16 k], transpose into Xs[k][row]
#pragma unroll
        for (int i = 0; i < 2; i++) {
            int idx = t + i * 256;         // 0..511
            int row = idx >> 2;            // 0..127
            int kq  = idx & 3;             // k = kq*4 .. +3
            int grow = rowbase + row;
            float4 v = make_float4(0.f, 0.f, 0.f, 0.f);
            if (grow < M)
                v = *(const float4*)(x + (size_t)grow * 128 + kb + kq * 4);
            Xs[(kq * 4 + 0) * XS_STRIDE + row] = v.x;
            Xs[(kq * 4 + 1) * XS_STRIDE + row] = v.y;
            Xs[(kq * 4 + 2) * XS_STRIDE + row] = v.z;
            Xs[(kq * 4 + 3) * XS_STRIDE + row] = v.w;
        }
        // load W slice [16 k x 128 n], duplicate
#pragma unroll
        for (int i = 0; i < 2; i++) {
            int idx = t + i * 256;
            int k = idx >> 5;              // 0..15
            int nq = idx & 31;             // n = nq*4 .. +3
            float4 w = *(const float4*)(W1 + (size_t)(kb + k) * 128 + nq * 4);
            Ws2[k * 128 + nq * 4 + 0] = dup2(w.x);
            Ws2[k * 128 + nq * 4 + 1] = dup2(w.y);
            Ws2[k * 128 + nq * 4 + 2] = dup2(w.z);
            Ws2[k * 128 + nq * 4 + 3] = dup2(w.w);
        }
        __syncthreads();
#pragma unroll
        for (int k = 0; k < 16; k++) {
            const float* xp = &Xs[k * XS_STRIDE + tidy * 8];
            ulonglong2 aA = *(const ulonglong2*)(xp);       // rows 0-3 (pairs)
            ulonglong2 aB = *(const ulonglong2*)(xp + 4);   // rows 4-7
            ull a[4] = {aA.x, aA.y, aB.x, aB.y};
            const ull* wp = &Ws2[k * 128 + tidx * 8];
            ull b[8];
#pragma unroll
            for (int j = 0; j < 4; j++) {
                ulonglong2 bv = *(const ulonglong2*)(wp + j * 2);
                b[j * 2]     = bv.x;
                b[j * 2 + 1] = bv.y;
            }
#pragma unroll
            for (int r = 0; r < 4; r++)
#pragma unroll
                for (int c = 0; c < 8; c++)
                    ffma2(acc[r][c], a[r], b[c]);
        }
        __syncthreads();
    }

    // epilogue: rows rowbase + tidy*8 + 2*r2 + {0,1}, cols tidx*8..+7
#pragma unroll
    for (int r2 = 0; r2 < 4; r2++) {
        float lo[8], hi[8];
#pragma unroll
        for (int c = 0; c < 8; c++) unpack2(lo[c], hi[c], acc[r2][c]);
        int row0 = rowbase + tidy * 8 + r2 * 2;
#pragma unroll
        for (int half = 0; half < 2; half++) {
            int grow = row0 + half;
            if (grow < M) {
                float* vals = half ? hi : lo;
                float s = g_dinv[grow]; s = s * s;
                float* hp = g_h    + (size_t)grow * 128 + tidx * 8;
                float* op = g_out1 + (size_t)grow * 128 + tidx * 8;
                float4 v0 = make_float4(vals[0], vals[1], vals[2], vals[3]);
                float4 v1 = make_float4(vals[4], vals[5], vals[6], vals[7]);
                *(float4*)hp       = v0;
                *((float4*)hp + 1) = v1;
                float4 w0 = make_float4(v0.x * s, v0.y * s, v0.z * s, v0.w * s);
                float4 w1 = make_float4(v1.x * s, v1.y * s, v1.z * s, v1.w * s);
                *(float4*)op       = w0;
                *((float4*)op + 1) = w1;
            }
        }
    }
}

// ---------------- scatter layer 1: one warp per edge (128 floats) ----------
__global__ __launch_bounds__(256) void k_scatter1(int e) {
    int warp = (blockIdx.x * blockDim.x + threadIdx.x) >> 5;
    int lane = threadIdx.x & 31;
    if (warp >= e) return;
    int2 rc = g_edge[warp];
    float nm = g_norm[warp];
    float4 v = *(const float4*)(g_h + (size_t)rc.x * 128 + lane * 4);
    v.x *= nm; v.y *= nm; v.z *= nm; v.w *= nm;
    red_add_v4(g_out1 + (size_t)rc.y * 128 + lane * 4, v);
}

// ---------------- GEMM2: t = relu(out1+b1) @ W2 ; out = b2 + t*dinv^2 ------
// 128x64 tile, 256 threads, thread = 4 rows x 8 cols via f32x2 (row pairs).
__global__ __launch_bounds__(256, 2) void k_gemm2(const float* __restrict__ W2,
                                                  const float* __restrict__ b1,
                                                  const float* __restrict__ b2,
                                                  float* __restrict__ out, int M) {
    __shared__ float Xs[16 * XS_STRIDE];   // [k][row]
    __shared__ ull   Ws2[16 * 64];         // [k][col], dup
    __shared__ float Bs1[128];
    __shared__ float Bs2[64];

    const int t = threadIdx.x;
    const int tidx = t & 7;                // col group: cols tidx*8 .. +7
    const int tidy = t >> 3;               // row group: rows tidy*4 .. +3
    const int rowbase = blockIdx.x * 128;

    if (t < 128) Bs1[t] = b1[t];
    if (t < 64)  Bs2[t] = b2[t];
    __syncthreads();

    ull acc[2][8];
#pragma unroll
    for (int r = 0; r < 2; r++)
#pragma unroll
        for (int c = 0; c < 8; c++) acc[r][c] = 0ull;

    for (int kb = 0; kb < 128; kb += 16) {
        // load X slice with bias+relu, transpose
#pragma unroll
        for (int i = 0; i < 2; i++) {
            int idx = t + i * 256;
            int row = idx >> 2;
            int kq  = idx & 3;
            int grow = rowbase + row;
            float4 v = make_float4(0.f, 0.f, 0.f, 0.f);
            if (grow < M) {
                v = *(const float4*)(g_out1 + (size_t)grow * 128 + kb + kq * 4);
                v.x = fmaxf(v.x + Bs1[kb + kq * 4 + 0], 0.f);
                v.y = fmaxf(v.y + Bs1[kb + kq * 4 + 1], 0.f);
                v.z = fmaxf(v.z + Bs1[kb + kq * 4 + 2], 0.f);
                v.w = fmaxf(v.w + Bs1[kb + kq * 4 + 3], 0.f);
            }
            Xs[(kq * 4 + 0) * XS_STRIDE + row] = v.x;
            Xs[(kq * 4 + 1) * XS_STRIDE + row] = v.y;
            Xs[(kq * 4 + 2) * XS_STRIDE + row] = v.z;
            Xs[(kq * 4 + 3) * XS_STRIDE + row] = v.w;
        }
        // load W2 slice [16 k x 64 n], duplicate
        {
            int k = t >> 4;                // 0..15
            int nq = t & 15;               // n = nq*4 .. +3
            float4 w = *(const float4*)(W2 + (size_t)(kb + k) * 64 + nq * 4);
            Ws2[k * 64 + nq * 4 + 0] = dup2(w.x);
            Ws2[k * 64 + nq * 4 + 1] = dup2(w.y);
            Ws2[k * 64 + nq * 4 + 2] = dup2(w.z);
            Ws2[k * 64 + nq * 4 + 3] = dup2(w.w);
        }
        __syncthreads();
#pragma unroll
        for (int k = 0; k < 16; k++) {
            const float* xp = &Xs[k * XS_STRIDE + tidy * 4];
            ulonglong2 aA = *(const ulonglong2*)(xp);   // rows 0-3 (2 pairs)
            ull a[2] = {aA.x, aA.y};
            const ull* wp = &Ws2[k * 64 + tidx * 8];
            ull b[8];
#pragma unroll
            for (int j = 0; j < 4; j++) {
                ulonglong2 bv = *(const ulonglong2*)(wp + j * 2);
                b[j * 2]     = bv.x;
                b[j * 2 + 1] = bv.y;
            }
#pragma unroll
            for (int r = 0; r < 2; r++)
#pragma unroll
                for (int c = 0; c < 8; c++)
                    ffma2(acc[r][c], a[r], b[c]);
        }
        __syncthreads();
    }

#pragma unroll
    for (int r2 = 0; r2 < 2; r2++) {
        float lo[8], hi[8];
#pragma unroll
        for (int c = 0; c < 8; c++) unpack2(lo[c], hi[c], acc[r2][c]);
        int row0 = rowbase + tidy * 4 + r2 * 2;
#pragma unroll
        for (int half = 0; half < 2; half++) {
            int grow = row0 + half;
            if (grow < M) {
                float* vals = half ? hi : lo;
                float s = g_dinv[grow]; s = s * s;
                float4 t0 = make_float4(vals[0], vals[1], vals[2], vals[3]);
                float4 t1 = make_float4(vals[4], vals[5], vals[6], vals[7]);
                float* tp = g_t + (size_t)grow * 64 + tidx * 8;
                *(float4*)tp       = t0;
                *((float4*)tp + 1) = t1;
                float4 o0, o1;
                o0.x = Bs2[tidx * 8 + 0] + t0.x * s;
                o0.y = Bs2[tidx * 8 + 1] + t0.y * s;
                o0.z = Bs2[tidx * 8 + 2] + t0.z * s;
                o0.w = Bs2[tidx * 8 + 3] + t0.w * s;
                o1.x = Bs2[tidx * 8 + 4] + t1.x * s;
                o1.y = Bs2[tidx * 8 + 5] + t1.y * s;
                o1.z = Bs2[tidx * 8 + 6] + t1.z * s;
                o1.w = Bs2[tidx * 8 + 7] + t1.w * s;
                float* op = out + (size_t)grow * 64 + tidx * 8;
                *(float4*)op       = o0;
                *((float4*)op + 1) = o1;
            }
        }
    }
}

// ---------------- scatter layer 2: half-warp per edge (64 floats) ----------
__global__ __launch_bounds__(256) void k_scatter2(float* __restrict__ out, int e) {
    int gid = blockIdx.x * blockDim.x + threadIdx.x;
    int edge = gid >> 4;
    int lane = gid & 15;
    if (edge >= e) return;
    int2 rc = g_edge[edge];
    float nm = g_norm[edge];
    float4 v = *(const float4*)(g_t + (size_t)rc.x * 64 + lane * 4);
    v.x *= nm; v.y *= nm; v.z *= nm; v.w *= nm;
    red_add_v4(out + (size_t)rc.y * 64 + lane * 4, v);
}

// ---------------- entry ----------------------------------------------------
extern "C" void kernel_launch(void* const* d_in, const int* in_sizes, int n_in,
                              void* d_out, int out_size) {
    const float* x  = (const float*)d_in[0];
    const void*  ei = d_in[1];                  // int64 or int32 (device-detected)
    const float* ew = (const float*)d_in[2];
    const float* W1 = (const float*)d_in[3];
    const float* b1 = (const float*)d_in[4];
    const float* W2 = (const float*)d_in[5];
    const float* b2 = (const float*)d_in[6];
    float* out = (float*)d_out;

    int N = in_sizes[0] / F_IN;     // 50000
    int E = in_sizes[2];            // 800000

    k_prep0    <<<(N + 255) / 256, 256>>>((const int*)ei, N);   // launch 0
    k_accum_deg<<<(E + 255) / 256, 256>>>(ei, ew, E);           // launch 1
    k_dinv     <<<(N + 255) / 256, 256>>>(N);                   // launch 2
    k_edge_prep<<<(E + 255) / 256, 256>>>(ei, ew, E);           // launch 3
    k_gemm1    <<<(N + 127) / 128, 256>>>(x, W1, N);            // launch 4
    k_scatter1 <<<(E + 7) / 8, 256>>>(E);                       // launch 5 (profiled)
    k_gemm2    <<<(N + 127) / 128, 256>>>(W2, b1, b2, out, N);  // launch 6
    k_scatter2 <<<(E + 15) / 16, 256>>>(out, E);                // launch 7
}

// round 3
// speedup vs baseline: 1.9226x; 1.9226x over previous
#include <cuda_runtime.h>

#define N_NODES_MAX 50000
#define E_MAX       800000
#define F_IN  128
#define F_HID 128
#define F_OUT 64

// ---------------- scratch (device globals; no allocation allowed) ----------
__device__ float g_deg  [N_NODES_MAX];
__device__ float g_dinv [N_NODES_MAX];
__device__ int   g_cnt  [N_NODES_MAX];
__device__ int   g_ptr  [N_NODES_MAX + 1];
__device__ int   g_cur  [N_NODES_MAX];
__device__ int   g_bsum [64];
__device__ int   g_bexcl[64];
__device__ int   g_srt_row [E_MAX];
__device__ float g_srt_norm[E_MAX];
__device__ float g_h   [(size_t)N_NODES_MAX * F_IN];   // x @ W1
__device__ float g_out1[(size_t)N_NODES_MAX * F_HID];  // layer-1 accum (self term + msgs)
__device__ float g_t   [(size_t)N_NODES_MAX * F_OUT];  // relu(h1) @ W2
__device__ int   g_is64;

// ---------------- helpers --------------------------------------------------
__device__ __forceinline__ int load_edge_idx(const void* ei, size_t pos) {
    if (g_is64) return (int)((const long long*)ei)[pos];
    return ((const int*)ei)[pos];
}

// ---------------- prep0: deg init, cnt zero, dtype detect ------------------
__global__ void k_prep0(const int* __restrict__ ei32, int n) {
    int i = blockIdx.x * blockDim.x + threadIdx.x;
    if (i < n) { g_deg[i] = 1.0f; g_cnt[i] = 0; }
    if (blockIdx.x == 0 && threadIdx.x < 32) {
        // int64 little-endian values in [0,50000): odd 32-bit words all zero
        int v = ei32[threadIdx.x * 2 + 1] | ei32[64 + threadIdx.x * 2 + 1];
        unsigned m = __ballot_sync(0xffffffffu, v != 0);
        if (threadIdx.x == 0) g_is64 = (m == 0u);
    }
}

// ---------------- weighted degree + histogram ------------------------------
__global__ void k_deg_hist(const void* __restrict__ ei,
                           const float* __restrict__ ew, int e) {
    int i = blockIdx.x * blockDim.x + threadIdx.x;
    if (i < e) {
        int c = load_edge_idx(ei, (size_t)e + i);
        atomicAdd(&g_deg[c], ew[i]);
        atomicAdd(&g_cnt[c], 1);
    }
}

__global__ void k_dinv(int n) {
    int i = blockIdx.x * blockDim.x + threadIdx.x;
    if (i < n) {
        float d = g_deg[i];
        g_dinv[i] = (d > 0.f) ? rsqrtf(d) : 0.f;
    }
}

// ---------------- scan (3 kernels): g_cnt -> exclusive g_ptr, g_cur --------
__global__ __launch_bounds__(1024) void k_scanA(int n) {
    __shared__ int s[1024];
    int i = blockIdx.x * 1024 + threadIdx.x;
    int v = (i < n) ? g_cnt[i] : 0;
    s[threadIdx.x] = v;
    __syncthreads();
#pragma unroll
    for (int off = 1; off < 1024; off <<= 1) {
        int t = (threadIdx.x >= off) ? s[threadIdx.x - off] : 0;
        __syncthreads();
        s[threadIdx.x] += t;
        __syncthreads();
    }
    if (i < n) g_ptr[i] = s[threadIdx.x];           // inclusive
    if (threadIdx.x == 1023) g_bsum[blockIdx.x] = s[1023];
}

__global__ void k_scanB(int nb) {
    __shared__ int s[64];
    int v = (threadIdx.x < nb) ? g_bsum[threadIdx.x] : 0;
    s[threadIdx.x] = v;
    __syncthreads();
#pragma unroll
    for (int off = 1; off < 64; off <<= 1) {
        int t = (threadIdx.x >= off) ? s[threadIdx.x - off] : 0;
        __syncthreads();
        s[threadIdx.x] += t;
        __syncthreads();
    }
    g_bexcl[threadIdx.x] = s[threadIdx.x] - v;      // exclusive
}

__global__ void k_scanC(int n) {
    int i = blockIdx.x * blockDim.x + threadIdx.x;
    if (i < n) {
        int excl = g_ptr[i] - g_cnt[i] + g_bexcl[i >> 10];
        g_ptr[i] = excl;
        g_cur[i] = excl;
        if (i == n - 1) g_ptr[n] = excl + g_cnt[i];
    }
}

// ---------------- edge placement into CSR ----------------------------------
__global__ void k_place(const void* __restrict__ ei,
                        const float* __restrict__ ew, int e) {
    int i = blockIdx.x * blockDim.x + threadIdx.x;
    if (i < e) {
        int r = load_edge_idx(ei, (size_t)i);
        int c = load_edge_idx(ei, (size_t)e + i);
        float nm = g_dinv[r] * ew[i] * g_dinv[c];
        int pos = atomicAdd(&g_cur[c], 1);
        g_srt_row[pos]  = r;
        g_srt_norm[pos] = nm;
    }
}

// ---------------- GEMM1: h = x @ W1 ; out1 = h * dinv^2 (self loop) --------
// tile 64 rows x 128 cols, 256 threads, 4x8 per thread (R1 known-good)
__global__ __launch_bounds__(256) void k_gemm1(const float* __restrict__ x,
                                               const float* __restrict__ W1,
                                               int M) {
    __shared__ float Xs[64][36];     // [row][k], padded
    __shared__ float Ws[32][128];    // [k][n]
    const int t = threadIdx.x;
    const int tidx = t & 15;         // cols tidx*8 .. +7
    const int tidy = t >> 4;         // rows tidy*4 .. +3
    const int rowbase = blockIdx.x * 64;

    float acc[4][8];
#pragma unroll
    for (int r = 0; r < 4; r++)
#pragma unroll
        for (int c = 0; c < 8; c++) acc[r][c] = 0.f;

    for (int kb = 0; kb < 128; kb += 32) {
#pragma unroll
        for (int i = 0; i < 2; i++) {              // 64x32 floats = 512 f4
            int idx = t + i * 256;
            int r = idx >> 3, kq = idx & 7;
            int grow = rowbase + r;
            float4 v = make_float4(0.f, 0.f, 0.f, 0.f);
            if (grow < M)
                v = *(const float4*)(x + (size_t)grow * 128 + kb + kq * 4);
            *(float4*)&Xs[r][kq * 4] = v;
        }
#pragma unroll
        for (int i = 0; i < 4; i++) {              // 32x128 floats = 1024 f4
            int idx = t + i * 256;
            int k = idx >> 5, nq = idx & 31;
            *(float4*)&Ws[k][nq * 4] =
                *(const float4*)(W1 + (size_t)(kb + k) * 128 + nq * 4);
        }
        __syncthreads();
#pragma unroll
        for (int k = 0; k < 32; k++) {
            float aa[4];
#pragma unroll
            for (int r = 0; r < 4; r++) aa[r] = Xs[tidy * 4 + r][k];
            float4 b0 = *(const float4*)&Ws[k][tidx * 8];
            float4 b1 = *(const float4*)&Ws[k][tidx * 8 + 4];
            float bb[8] = {b0.x, b0.y, b0.z, b0.w, b1.x, b1.y, b1.z, b1.w};
#pragma unroll
            for (int r = 0; r < 4; r++)
#pragma unroll
                for (int c = 0; c < 8; c++)
                    acc[r][c] = fmaf(aa[r], bb[c], acc[r][c]);
        }
        __syncthreads();
    }

#pragma unroll
    for (int r = 0; r < 4; r++) {
        int grow = rowbase + tidy * 4 + r;
        if (grow < M) {
            float s = g_dinv[grow]; s = s * s;
            float* hp = g_h    + (size_t)grow * 128 + tidx * 8;
            float* op = g_out1 + (size_t)grow * 128 + tidx * 8;
            float4 v0 = make_float4(acc[r][0], acc[r][1], acc[r][2], acc[r][3]);
            float4 v1 = make_float4(acc[r][4], acc[r][5], acc[r][6], acc[r][7]);
            *(float4*)hp       = v0;
            *((float4*)hp + 1) = v1;
            float4 w0 = make_float4(v0.x * s, v0.y * s, v0.z * s, v0.w * s);
            float4 w1 = make_float4(v1.x * s, v1.y * s, v1.z * s, v1.w * s);
            *(float4*)op       = w0;
            *((float4*)op + 1) = w1;
        }
    }
}

// ---------------- agg layer 1: warp per destination node (128 feats) -------
__global__ __launch_bounds__(256) void k_agg1(int n) {
    int c = blockIdx.x * 8 + (threadIdx.x >> 5);
    if (c >= n) return;
    int lane = threadIdx.x & 31;
    int beg = g_ptr[c], end = g_ptr[c + 1];
    float4 acc = make_float4(0.f, 0.f, 0.f, 0.f);
    for (int e = beg; e < end; e++) {
        int   r  = g_srt_row[e];
        float nm = g_srt_norm[e];
        float4 v = *(const float4*)(g_h + (size_t)r * 128 + lane * 4);
        acc.x = fmaf(v.x, nm, acc.x);
        acc.y = fmaf(v.y, nm, acc.y);
        acc.z = fmaf(v.z, nm, acc.z);
        acc.w = fmaf(v.w, nm, acc.w);
    }
    float* op = g_out1 + (size_t)c * 128 + lane * 4;
    float4 cur = *(float4*)op;
    cur.x += acc.x; cur.y += acc.y; cur.z += acc.z; cur.w += acc.w;
    *(float4*)op = cur;
}

// ---------------- GEMM2: t = relu(out1+b1) @ W2 ; out = b2 + t*dinv^2 ------
// tile 64 rows x 64 cols, 256 threads, 4x4 per thread (R1 known-good)
__global__ __launch_bounds__(256) void k_gemm2(const float* __restrict__ W2,
                                               const float* __restrict__ b1,
                                               const float* __restrict__ b2,
                                               float* __restrict__ out, int M) {
    __shared__ float Xs[64][36];
    __shared__ float Ws[32][64];
    __shared__ float Bs1[128];
    __shared__ float Bs2[64];
    const int t = threadIdx.x;
    const int tidx = t & 15;         // cols tidx*4 .. +3
    const int tidy = t >> 4;         // rows tidy*4 .. +3
    const int rowbase = blockIdx.x * 64;

    if (t < 128) Bs1[t] = b1[t];
    if (t < 64)  Bs2[t] = b2[t];
    __syncthreads();

    float acc[4][4];
#pragma unroll
    for (int r = 0; r < 4; r++)
#pragma unroll
        for (int c = 0; c < 4; c++) acc[r][c] = 0.f;

    for (int kb = 0; kb < 128; kb += 32) {
#pragma unroll
        for (int i = 0; i < 2; i++) {              // A tile with bias+relu
            int idx = t + i * 256;
            int r = idx >> 3, kq = idx & 7;
            int grow = rowbase + r;
            float4 v = make_float4(0.f, 0.f, 0.f, 0.f);
            if (grow < M) {
                v = *(const float4*)(g_out1 + (size_t)grow * 128 + kb + kq * 4);
                v.x = fmaxf(v.x + Bs1[kb + kq * 4 + 0], 0.f);
                v.y = fmaxf(v.y + Bs1[kb + kq * 4 + 1], 0.f);
                v.z = fmaxf(v.z + Bs1[kb + kq * 4 + 2], 0.f);
                v.w = fmaxf(v.w + Bs1[kb + kq * 4 + 3], 0.f);
            }
            *(float4*)&Xs[r][kq * 4] = v;
        }
#pragma unroll
        for (int i = 0; i < 2; i++) {              // 32x64 floats = 512 f4
            int idx = t + i * 256;
            int k = idx >> 4, nq = idx & 15;
            *(float4*)&Ws[k][nq * 4] =
                *(const float4*)(W2 + (size_t)(kb + k) * 64 + nq * 4);
        }
        __syncthreads();
#pragma unroll
        for (int k = 0; k < 32; k++) {
            float aa[4];
#pragma unroll
            for (int r = 0; r < 4; r++) aa[r] = Xs[tidy * 4 + r][k];
            float4 b = *(const float4*)&Ws[k][tidx * 4];
            float bb[4] = {b.x, b.y, b.z, b.w};
#pragma unroll
            for (int r = 0; r < 4; r++)
#pragma unroll
                for (int c = 0; c < 4; c++)
                    acc[r][c] = fmaf(aa[r], bb[c], acc[r][c]);
        }
        __syncthreads();
    }

#pragma unroll
    for (int r = 0; r < 4; r++) {
        int grow = rowbase + tidy * 4 + r;
        if (grow < M) {
            float s = g_dinv[grow]; s = s * s;
            float4 tv = make_float4(acc[r][0], acc[r][1], acc[r][2], acc[r][3]);
            *(float4*)(g_t + (size_t)grow * 64 + tidx * 4) = tv;
            float4 ov;
            ov.x = Bs2[tidx * 4 + 0] + tv.x * s;
            ov.y = Bs2[tidx * 4 + 1] + tv.y * s;
            ov.z = Bs2[tidx * 4 + 2] + tv.z * s;
            ov.w = Bs2[tidx * 4 + 3] + tv.w * s;
            *(float4*)(out + (size_t)grow * 64 + tidx * 4) = ov;
        }
    }
}

// ---------------- agg layer 2: warp per destination node (64 feats) --------
__global__ __launch_bounds__(256) void k_agg2(float* __restrict__ out, int n) {
    int c = blockIdx.x * 8 + (threadIdx.x >> 5);
    if (c >= n) return;
    int lane = threadIdx.x & 31;
    int beg = g_ptr[c], end = g_ptr[c + 1];
    float2 acc = make_float2(0.f, 0.f);
    for (int e = beg; e < end; e++) {
        int   r  = g_srt_row[e];
        float nm = g_srt_norm[e];
        float2 v = *(const float2*)(g_t + (size_t)r * 64 + lane * 2);
        acc.x = fmaf(v.x, nm, acc.x);
        acc.y = fmaf(v.y, nm, acc.y);
    }
    float* op = out + (size_t)c * 64 + lane * 2;
    float2 cur = *(float2*)op;
    cur.x += acc.x; cur.y += acc.y;
    *(float2*)op = cur;
}

// ---------------- entry ----------------------------------------------------
extern "C" void kernel_launch(void* const* d_in, const int* in_sizes, int n_in,
                              void* d_out, int out_size) {
    const float* x  = (const float*)d_in[0];
    const void*  ei = d_in[1];                  // int64 or int32 (device-detected)
    const float* ew = (const float*)d_in[2];
    const float* W1 = (const float*)d_in[3];
    const float* b1 = (const float*)d_in[4];
    const float* W2 = (const float*)d_in[5];
    const float* b2 = (const float*)d_in[6];
    float* out = (float*)d_out;

    int N = in_sizes[0] / F_IN;     // 50000
    int E = in_sizes[2];            // 800000
    int nScanBlocks = (N + 1023) / 1024;

    k_prep0   <<<(N + 255) / 256, 256>>>((const int*)ei, N);    // 0
    k_deg_hist<<<(E + 255) / 256, 256>>>(ei, ew, E);            // 1
    k_dinv    <<<(N + 255) / 256, 256>>>(N);                    // 2
    k_gemm1   <<<(N + 63) / 64, 256>>>(x, W1, N);               // 3 (profiled slot)
    k_scanA   <<<nScanBlocks, 1024>>>(N);                       // 4
    k_scanB   <<<1, 64>>>(nScanBlocks);                         // 5
    k_scanC   <<<(N + 255) / 256, 256>>>(N);                    // 6
    k_place   <<<(E + 255) / 256, 256>>>(ei, ew, E);            // 7
    k_agg1    <<<(N + 7) / 8, 256>>>(N);                        // 8
    k_gemm2   <<<(N + 63) / 64, 256>>>(W2, b1, b2, out, N);     // 9
    k_agg2    <<<(N + 7) / 8, 256>>>(out, N);                   // 10
}

// round 4
// speedup vs baseline: 2.0640x; 1.0735x over previous
#include <cuda_runtime.h>

#define N_NODES_MAX 50000
#define E_MAX       800000
#define F_IN  128
#define F_HID 128
#define F_OUT 64

// ---------------- scratch (device globals; no allocation allowed) ----------
__device__ float g_deg  [N_NODES_MAX];
__device__ float g_dinv [N_NODES_MAX];
__device__ int   g_cnt  [N_NODES_MAX];
__device__ int   g_ptr  [N_NODES_MAX + 1];
__device__ int   g_cur  [N_NODES_MAX];
__device__ int   g_bsum [64];
__device__ int   g_bexcl[64];
__device__ int   g_srt_row [E_MAX];
__device__ float g_srt_norm[E_MAX];
__device__ float g_h   [(size_t)N_NODES_MAX * F_IN];   // x @ W1
__device__ float g_out1[(size_t)N_NODES_MAX * F_HID];  // layer-1 accum (self + msgs)
__device__ float g_t   [(size_t)N_NODES_MAX * F_OUT];  // relu(h1) @ W2
__device__ int   g_is64;

// ---------------- helpers --------------------------------------------------
__device__ __forceinline__ int load_edge_idx(const void* ei, size_t pos) {
    if (g_is64) return (int)((const long long*)ei)[pos];
    return ((const int*)ei)[pos];
}

// ---------------- prep0: deg init, cnt zero, dtype detect ------------------
__global__ void k_prep0(const int* __restrict__ ei32, int n) {
    int i = blockIdx.x * blockDim.x + threadIdx.x;
    if (i < n) { g_deg[i] = 1.0f; g_cnt[i] = 0; }
    if (blockIdx.x == 0 && threadIdx.x < 32) {
        // int64 little-endian values in [0,50000): odd 32-bit words all zero
        int v = ei32[threadIdx.x * 2 + 1] | ei32[64 + threadIdx.x * 2 + 1];
        unsigned m = __ballot_sync(0xffffffffu, v != 0);
        if (threadIdx.x == 0) g_is64 = (m == 0u);
    }
}

// ---------------- weighted degree + histogram ------------------------------
__global__ void k_deg_hist(const void* __restrict__ ei,
                           const float* __restrict__ ew, int e) {
    int i = blockIdx.x * blockDim.x + threadIdx.x;
    if (i < e) {
        int c = load_edge_idx(ei, (size_t)e + i);
        atomicAdd(&g_deg[c], ew[i]);
        atomicAdd(&g_cnt[c], 1);
    }
}

__global__ void k_dinv(int n) {
    int i = blockIdx.x * blockDim.x + threadIdx.x;
    if (i < n) {
        float d = g_deg[i];
        g_dinv[i] = (d > 0.f) ? rsqrtf(d) : 0.f;
    }
}

// ---------------- scan (3 kernels): g_cnt -> exclusive g_ptr, g_cur --------
__global__ __launch_bounds__(1024) void k_scanA(int n) {
    __shared__ int s[1024];
    int i = blockIdx.x * 1024 + threadIdx.x;
    int v = (i < n) ? g_cnt[i] : 0;
    s[threadIdx.x] = v;
    __syncthreads();
#pragma unroll
    for (int off = 1; off < 1024; off <<= 1) {
        int t = (threadIdx.x >= off) ? s[threadIdx.x - off] : 0;
        __syncthreads();
        s[threadIdx.x] += t;
        __syncthreads();
    }
    if (i < n) g_ptr[i] = s[threadIdx.x];           // inclusive
    if (threadIdx.x == 1023) g_bsum[blockIdx.x] = s[1023];
}

__global__ void k_scanB(int nb) {
    __shared__ int s[64];
    int v = (threadIdx.x < nb) ? g_bsum[threadIdx.x] : 0;
    s[threadIdx.x] = v;
    __syncthreads();
#pragma unroll
    for (int off = 1; off < 64; off <<= 1) {
        int t = (threadIdx.x >= off) ? s[threadIdx.x - off] : 0;
        __syncthreads();
        s[threadIdx.x] += t;
        __syncthreads();
    }
    g_bexcl[threadIdx.x] = s[threadIdx.x] - v;      // exclusive
}

__global__ void k_scanC(int n) {
    int i = blockIdx.x * blockDim.x + threadIdx.x;
    if (i < n) {
        int excl = g_ptr[i] - g_cnt[i] + g_bexcl[i >> 10];
        g_ptr[i] = excl;
        g_cur[i] = excl;
        if (i == n - 1) g_ptr[n] = excl + g_cnt[i];
    }
}

// ---------------- edge placement into CSR ----------------------------------
__global__ void k_place(const void* __restrict__ ei,
                        const float* __restrict__ ew, int e) {
    int i = blockIdx.x * blockDim.x + threadIdx.x;
    if (i < e) {
        int r = load_edge_idx(ei, (size_t)i);
        int c = load_edge_idx(ei, (size_t)e + i);
        float nm = g_dinv[r] * ew[i] * g_dinv[c];
        int pos = atomicAdd(&g_cur[c], 1);
        g_srt_row[pos]  = r;
        g_srt_norm[pos] = nm;
    }
}

// ---------------- GEMM1: h = x @ W1 ; out1 = h * dinv^2 (self loop) --------
// 128x128 tile, BK=16, 256 threads, 8x8 microtile (4+4 split), double-buffer
__global__ __launch_bounds__(256) void k_gemm1(const float* __restrict__ x,
                                               const float* __restrict__ W1,
                                               int M) {
    __shared__ float Xs[2][16][132];   // [buf][k][row], transposed A
    __shared__ float Ws[2][16][128];   // [buf][k][n]

    const int t  = threadIdx.x;
    const int tx = t & 15;             // col group
    const int ty = t >> 4;             // row group
    const int rowbase = blockIdx.x * 128;

    // global load coords: X tile 128x16 (2 float4/thread), W tile 16x128 (2/thread)
    const int xrow = t >> 2, xkq = t & 3;     // rows xrow, xrow+64
    const int wk   = t >> 5, wnq = t & 31;    // k wk, wk+8

    float4 vx0, vx1, vw0, vw1;

    float acc[8][8];
#pragma unroll
    for (int r = 0; r < 8; r++)
#pragma unroll
        for (int c = 0; c < 8; c++) acc[r][c] = 0.f;

    // prologue: stage 0
    {
        int g0 = rowbase + xrow, g1 = rowbase + xrow + 64;
        vx0 = (g0 < M) ? *(const float4*)(x + (size_t)g0 * 128 + xkq * 4)
                       : make_float4(0.f, 0.f, 0.f, 0.f);
        vx1 = (g1 < M) ? *(const float4*)(x + (size_t)g1 * 128 + xkq * 4)
                       : make_float4(0.f, 0.f, 0.f, 0.f);
        vw0 = *(const float4*)(W1 + (size_t)wk * 128 + wnq * 4);
        vw1 = *(const float4*)(W1 + (size_t)(wk + 8) * 128 + wnq * 4);
        Xs[0][xkq * 4 + 0][xrow] = vx0.x;
        Xs[0][xkq * 4 + 1][xrow] = vx0.y;
        Xs[0][xkq * 4 + 2][xrow] = vx0.z;
        Xs[0][xkq * 4 + 3][xrow] = vx0.w;
        Xs[0][xkq * 4 + 0][xrow + 64] = vx1.x;
        Xs[0][xkq * 4 + 1][xrow + 64] = vx1.y;
        Xs[0][xkq * 4 + 2][xrow + 64] = vx1.z;
        Xs[0][xkq * 4 + 3][xrow + 64] = vx1.w;
        *(float4*)&Ws[0][wk][wnq * 4]     = vw0;
        *(float4*)&Ws[0][wk + 8][wnq * 4] = vw1;
    }
    __syncthreads();

    for (int s = 0; s < 8; s++) {
        const int cur = s & 1;
        if (s < 7) {                               // prefetch next tile to regs
            int kb = (s + 1) * 16;
            int g0 = rowbase + xrow, g1 = rowbase + xrow + 64;
            vx0 = (g0 < M) ? *(const float4*)(x + (size_t)g0 * 128 + kb + xkq * 4)
                           : make_float4(0.f, 0.f, 0.f, 0.f);
            vx1 = (g1 < M) ? *(const float4*)(x + (size_t)g1 * 128 + kb + xkq * 4)
                           : make_float4(0.f, 0.f, 0.f, 0.f);
            vw0 = *(const float4*)(W1 + (size_t)(kb + wk) * 128 + wnq * 4);
            vw1 = *(const float4*)(W1 + (size_t)(kb + wk + 8) * 128 + wnq * 4);
        }
#pragma unroll
        for (int k = 0; k < 16; k++) {
            float4 A0 = *(const float4*)&Xs[cur][k][ty * 4];
            float4 A1 = *(const float4*)&Xs[cur][k][64 + ty * 4];
            float4 B0 = *(const float4*)&Ws[cur][k][tx * 4];
            float4 B1 = *(const float4*)&Ws[cur][k][64 + tx * 4];
            float a[8] = {A0.x, A0.y, A0.z, A0.w, A1.x, A1.y, A1.z, A1.w};
            float b[8] = {B0.x, B0.y, B0.z, B0.w, B1.x, B1.y, B1.z, B1.w};
#pragma unroll
            for (int r = 0; r < 8; r++)
#pragma unroll
                for (int c = 0; c < 8; c++)
                    acc[r][c] = fmaf(a[r], b[c], acc[r][c]);
        }
        if (s < 7) {                               // store to idle buffer
            const int nxt = cur ^ 1;
            Xs[nxt][xkq * 4 + 0][xrow] = vx0.x;
            Xs[nxt][xkq * 4 + 1][xrow] = vx0.y;
            Xs[nxt][xkq * 4 + 2][xrow] = vx0.z;
            Xs[nxt][xkq * 4 + 3][xrow] = vx0.w;
            Xs[nxt][xkq * 4 + 0][xrow + 64] = vx1.x;
            Xs[nxt][xkq * 4 + 1][xrow + 64] = vx1.y;
            Xs[nxt][xkq * 4 + 2][xrow + 64] = vx1.z;
            Xs[nxt][xkq * 4 + 3][xrow + 64] = vx1.w;
            *(float4*)&Ws[nxt][wk][wnq * 4]     = vw0;
            *(float4*)&Ws[nxt][wk + 8][wnq * 4] = vw1;
        }
        __syncthreads();
    }

    // epilogue
#pragma unroll
    for (int rh = 0; rh < 2; rh++)
#pragma unroll
        for (int ri = 0; ri < 4; ri++) {
            int grow = rowbase + rh * 64 + ty * 4 + ri;
            if (grow < M) {
                int r = rh * 4 + ri;
                float sc = g_dinv[grow]; sc = sc * sc;
                float4 v0 = make_float4(acc[r][0], acc[r][1], acc[r][2], acc[r][3]);
                float4 v1 = make_float4(acc[r][4], acc[r][5], acc[r][6], acc[r][7]);
                float* hp = g_h    + (size_t)grow * 128;
                float* op = g_out1 + (size_t)grow * 128;
                *(float4*)(hp + tx * 4)      = v0;
                *(float4*)(hp + 64 + tx * 4) = v1;
                float4 w0 = make_float4(v0.x * sc, v0.y * sc, v0.z * sc, v0.w * sc);
                float4 w1 = make_float4(v1.x * sc, v1.y * sc, v1.z * sc, v1.w * sc);
                *(float4*)(op + tx * 4)      = w0;
                *(float4*)(op + 64 + tx * 4) = w1;
            }
        }
}

// ---------------- agg layer 1: warp per destination node (128 feats) -------
__global__ __launch_bounds__(256) void k_agg1(int n) {
    int c = blockIdx.x * 8 + (threadIdx.x >> 5);
    if (c >= n) return;
    int lane = threadIdx.x & 31;
    int beg = g_ptr[c], end = g_ptr[c + 1];
    float4 acc = make_float4(0.f, 0.f, 0.f, 0.f);
    for (int e = beg; e < end; e++) {
        int   r  = g_srt_row[e];
        float nm = g_srt_norm[e];
        float4 v = *(const float4*)(g_h + (size_t)r * 128 + lane * 4);
        acc.x = fmaf(v.x, nm, acc.x);
        acc.y = fmaf(v.y, nm, acc.y);
        acc.z = fmaf(v.z, nm, acc.z);
        acc.w = fmaf(v.w, nm, acc.w);
    }
    float* op = g_out1 + (size_t)c * 128 + lane * 4;
    float4 cur = *(float4*)op;
    cur.x += acc.x; cur.y += acc.y; cur.z += acc.z; cur.w += acc.w;
    *(float4*)op = cur;
}

// ---------------- GEMM2: t = relu(out1+b1) @ W2 ; out = b2 + t*dinv^2 ------
// 128x64 tile, BK=16, 256 threads, 8x4 microtile (4+4 rows), double-buffer
__global__ __launch_bounds__(256) void k_gemm2(const float* __restrict__ W2,
                                               const float* __restrict__ b1,
                                               const float* __restrict__ b2,
                                               float* __restrict__ out, int M) {
    __shared__ float Xs[2][16][132];   // [buf][k][row]
    __shared__ float Ws[2][16][64];    // [buf][k][n]

    const int t  = threadIdx.x;
    const int tx = t & 15;             // cols tx*4 .. +3
    const int ty = t >> 4;             // rows ty*4, 64+ty*4
    const int rowbase = blockIdx.x * 128;

    const int xrow = t >> 2, xkq = t & 3;
    const int wk   = t >> 4, wnq = t & 15;    // 1 float4/thread for W2 tile

    float4 vx0, vx1, vw0;

    float acc[8][4];
#pragma unroll
    for (int r = 0; r < 8; r++)
#pragma unroll
        for (int c = 0; c < 4; c++) acc[r][c] = 0.f;

    // A load with fused bias+relu
    auto loadA = [&](int kb, int grow) -> float4 {
        float4 v = make_float4(0.f, 0.f, 0.f, 0.f);
        if (grow < M) {
            v = *(const float4*)(g_out1 + (size_t)grow * 128 + kb + xkq * 4);
            v.x = fmaxf(v.x + __ldg(b1 + kb + xkq * 4 + 0), 0.f);
            v.y = fmaxf(v.y + __ldg(b1 + kb + xkq * 4 + 1), 0.f);
            v.z = fmaxf(v.z + __ldg(b1 + kb + xkq * 4 + 2), 0.f);
            v.w = fmaxf(v.w + __ldg(b1 + kb + xkq * 4 + 3), 0.f);
        }
        return v;
    };

    {
        vx0 = loadA(0, rowbase + xrow);
        vx1 = loadA(0, rowbase + xrow + 64);
        vw0 = *(const float4*)(W2 + (size_t)wk * 64 + wnq * 4);
        Xs[0][xkq * 4 + 0][xrow] = vx0.x;
        Xs[0][xkq * 4 + 1][xrow] = vx0.y;
        Xs[0][xkq * 4 + 2][xrow] = vx0.z;
        Xs[0][xkq * 4 + 3][xrow] = vx0.w;
        Xs[0][xkq * 4 + 0][xrow + 64] = vx1.x;
        Xs[0][xkq * 4 + 1][xrow + 64] = vx1.y;
        Xs[0][xkq * 4 + 2][xrow + 64] = vx1.z;
        Xs[0][xkq * 4 + 3][xrow + 64] = vx1.w;
        *(float4*)&Ws[0][wk][wnq * 4] = vw0;
    }
    __syncthreads();

    for (int s = 0; s < 8; s++) {
        const int cur = s & 1;
        if (s < 7) {
            int kb = (s + 1) * 16;
            vx0 = loadA(kb, rowbase + xrow);
            vx1 = loadA(kb, rowbase + xrow + 64);
            vw0 = *(const float4*)(W2 + (size_t)(kb + wk) * 64 + wnq * 4);
        }
#pragma unroll
        for (int k = 0; k < 16; k++) {
            float4 A0 = *(const float4*)&Xs[cur][k][ty * 4];
            float4 A1 = *(const float4*)&Xs[cur][k][64 + ty * 4];
            float4 B0 = *(const float4*)&Ws[cur][k][tx * 4];
            float a[8] = {A0.x, A0.y, A0.z, A0.w, A1.x, A1.y, A1.z, A1.w};
            float b[4] = {B0.x, B0.y, B0.z, B0.w};
#pragma unroll
            for (int r = 0; r < 8; r++)
#pragma unroll
                for (int c = 0; c < 4; c++)
                    acc[r][c] = fmaf(a[r], b[c], acc[r][c]);
        }
        if (s < 7) {
            const int nxt = cur ^ 1;
            Xs[nxt][xkq * 4 + 0][xrow] = vx0.x;
            Xs[nxt][xkq * 4 + 1][xrow] = vx0.y;
            Xs[nxt][xkq * 4 + 2][xrow] = vx0.z;
            Xs[nxt][xkq * 4 + 3][xrow] = vx0.w;
            Xs[nxt][xkq * 4 + 0][xrow + 64] = vx1.x;
            Xs[nxt][xkq * 4 + 1][xrow + 64] = vx1.y;
            Xs[nxt][xkq * 4 + 2][xrow + 64] = vx1.z;
            Xs[nxt][xkq * 4 + 3][xrow + 64] = vx1.w;
            *(float4*)&Ws[nxt][wk][wnq * 4] = vw0;
        }
        __syncthreads();
    }

#pragma unroll
    for (int rh = 0; rh < 2; rh++)
#pragma unroll
        for (int ri = 0; ri < 4; ri++) {
            int grow = rowbase + rh * 64 + ty * 4 + ri;
            if (grow < M) {
                int r = rh * 4 + ri;
                float sc = g_dinv[grow]; sc = sc * sc;
                float4 tv = make_float4(acc[r][0], acc[r][1], acc[r][2], acc[r][3]);
                *(float4*)(g_t + (size_t)grow * 64 + tx * 4) = tv;
                float4 ov;
                ov.x = __ldg(b2 + tx * 4 + 0) + tv.x * sc;
                ov.y = __ldg(b2 + tx * 4 + 1) + tv.y * sc;
                ov.z = __ldg(b2 + tx * 4 + 2) + tv.z * sc;
                ov.w = __ldg(b2 + tx * 4 + 3) + tv.w * sc;
                *(float4*)(out + (size_t)grow * 64 + tx * 4) = ov;
            }
        }
}

// ---------------- agg layer 2: warp per destination node (64 feats) --------
__global__ __launch_bounds__(256) void k_agg2(float* __restrict__ out, int n) {
    int c = blockIdx.x * 8 + (threadIdx.x >> 5);
    if (c >= n) return;
    int lane = threadIdx.x & 31;
    int beg = g_ptr[c], end = g_ptr[c + 1];
    float2 acc = make_float2(0.f, 0.f);
    for (int e = beg; e < end; e++) {
        int   r  = g_srt_row[e];
        float nm = g_srt_norm[e];
        float2 v = *(const float2*)(g_t + (size_t)r * 64 + lane * 2);
        acc.x = fmaf(v.x, nm, acc.x);
        acc.y = fmaf(v.y, nm, acc.y);
    }
    float* op = out + (size_t)c * 64 + lane * 2;
    float2 cur = *(float2*)op;
    cur.x += acc.x; cur.y += acc.y;
    *(float2*)op = cur;
}

// ---------------- entry ----------------------------------------------------
extern "C" void kernel_launch(void* const* d_in, const int* in_sizes, int n_in,
                              void* d_out, int out_size) {
    const float* x  = (const float*)d_in[0];
    const void*  ei = d_in[1];                  // int64 or int32 (device-detected)
    const float* ew = (const float*)d_in[2];
    const float* W1 = (const float*)d_in[3];
    const float* b1 = (const float*)d_in[4];
    const float* W2 = (const float*)d_in[5];
    const float* b2 = (const float*)d_in[6];
    float* out = (float*)d_out;

    int N = in_sizes[0] / F_IN;     // 50000
    int E = in_sizes[2];            // 800000
    int nScanBlocks = (N + 1023) / 1024;

    k_prep0   <<<(N + 255) / 256, 256>>>((const int*)ei, N);    // 0
    k_deg_hist<<<(E + 255) / 256, 256>>>(ei, ew, E);            // 1
    k_dinv    <<<(N + 255) / 256, 256>>>(N);                    // 2
    k_gemm1   <<<(N + 127) / 128, 256>>>(x, W1, N);             // 3 (profiled slot)
    k_scanA   <<<nScanBlocks, 1024>>>(N);                       // 4
    k_scanB   <<<1, 64>>>(nScanBlocks);                         // 5
    k_scanC   <<<(N + 255) / 256, 256>>>(N);                    // 6
    k_place   <<<(E + 255) / 256, 256>>>(ei, ew, E);            // 7
    k_agg1    <<<(N + 7) / 8, 256>>>(N);                        // 8
    k_gemm2   <<<(N + 63) / 64, 256>>>(W2, b1, b2, out, N);     // 9
    k_agg2    <<<(N + 7) / 8, 256>>>(out, N);                   // 10
}

// round 6
// speedup vs baseline: 2.2950x; 1.1119x over previous
#include <cuda_runtime.h>
#include <cuda_bf16.h>
#include <cstdint>

#define N_NODES_MAX 50000
#define E_MAX       800000
#define F_IN  128
#define F_HID 128
#define F_OUT 64

// ---------------- scratch (device globals; no allocation allowed) ----------
__device__ float g_deg  [N_NODES_MAX];
__device__ float g_dinv [N_NODES_MAX];
__device__ int   g_cnt  [N_NODES_MAX];
__device__ int   g_ptr  [N_NODES_MAX + 1];
__device__ int   g_cur  [N_NODES_MAX];
__device__ int   g_bsum [64];
__device__ int   g_bexcl[64];
__device__ int2  g_srt  [E_MAX];                       // (row, norm-as-int)
__device__ float g_h   [(size_t)N_NODES_MAX * F_IN];   // x @ W1
__device__ float g_out1[(size_t)N_NODES_MAX * F_HID];  // layer-1 accum
__device__ float g_t   [(size_t)N_NODES_MAX * F_OUT];  // relu(h1) @ W2
__device__ int   g_is64;

// ---------------- helpers --------------------------------------------------
__device__ __forceinline__ int load_edge_idx(const void* ei, size_t pos) {
    if (g_is64) return (int)((const long long*)ei)[pos];
    return ((const int*)ei)[pos];
}

// split a pair of floats into packed bf16x2 (hi) and bf16x2 (residual lo)
__device__ __forceinline__ void split_pair(float a, float b,
                                           uint32_t& hi, uint32_t& lo) {
    __nv_bfloat16 ha = __float2bfloat16(a);
    __nv_bfloat16 hb = __float2bfloat16(b);
    float la = a - __bfloat162float(ha);
    float lb = b - __bfloat162float(hb);
    __nv_bfloat162 hp; hp.x = ha; hp.y = hb;
    __nv_bfloat162 lp; lp.x = __float2bfloat16(la); lp.y = __float2bfloat16(lb);
    hi = *reinterpret_cast<uint32_t*>(&hp);
    lo = *reinterpret_cast<uint32_t*>(&lp);
}

#define MMA_BF16(c, a0, a1, a2, a3, b0, b1)                                    \
    asm volatile("mma.sync.aligned.m16n8k16.row.col.f32.bf16.bf16.f32 "        \
                 "{%0,%1,%2,%3}, {%4,%5,%6,%7}, {%8,%9}, {%0,%1,%2,%3};"       \
                 : "+f"((c)[0]), "+f"((c)[1]), "+f"((c)[2]), "+f"((c)[3])      \
                 : "r"(a0), "r"(a1), "r"(a2), "r"(a3), "r"(b0), "r"(b1))

// ---------------- prep -------------------------------------------------------
__global__ void k_prep0(const int* __restrict__ ei32, int n) {
    int i = blockIdx.x * blockDim.x + threadIdx.x;
    if (i < n) { g_deg[i] = 1.0f; g_cnt[i] = 0; }
    if (blockIdx.x == 0 && threadIdx.x < 32) {
        int v = ei32[threadIdx.x * 2 + 1] | ei32[64 + threadIdx.x * 2 + 1];
        unsigned m = __ballot_sync(0xffffffffu, v != 0);
        if (threadIdx.x == 0) g_is64 = (m == 0u);
    }
}

__global__ void k_deg_hist(const void* __restrict__ ei,
                           const float* __restrict__ ew, int e) {
    int i = blockIdx.x * blockDim.x + threadIdx.x;
    if (i < e) {
        int c = load_edge_idx(ei, (size_t)e + i);
        atomicAdd(&g_deg[c], ew[i]);
        atomicAdd(&g_cnt[c], 1);
    }
}

__global__ void k_dinv(int n) {
    int i = blockIdx.x * blockDim.x + threadIdx.x;
    if (i < n) {
        float d = g_deg[i];
        g_dinv[i] = (d > 0.f) ? rsqrtf(d) : 0.f;
    }
}

__global__ __launch_bounds__(1024) void k_scanA(int n) {
    __shared__ int s[1024];
    int i = blockIdx.x * 1024 + threadIdx.x;
    int v = (i < n) ? g_cnt[i] : 0;
    s[threadIdx.x] = v;
    __syncthreads();
#pragma unroll
    for (int off = 1; off < 1024; off <<= 1) {
        int t = (threadIdx.x >= off) ? s[threadIdx.x - off] : 0;
        __syncthreads();
        s[threadIdx.x] += t;
        __syncthreads();
    }
    if (i < n) g_ptr[i] = s[threadIdx.x];
    if (threadIdx.x == 1023) g_bsum[blockIdx.x] = s[1023];
}

__global__ void k_scanB(int nb) {
    __shared__ int s[64];
    int v = (threadIdx.x < nb) ? g_bsum[threadIdx.x] : 0;
    s[threadIdx.x] = v;
    __syncthreads();
#pragma unroll
    for (int off = 1; off < 64; off <<= 1) {
        int t = (threadIdx.x >= off) ? s[threadIdx.x - off] : 0;
        __syncthreads();
        s[threadIdx.x] += t;
        __syncthreads();
    }
    g_bexcl[threadIdx.x] = s[threadIdx.x] - v;
}

__global__ void k_scanC(int n) {
    int i = blockIdx.x * blockDim.x + threadIdx.x;
    if (i < n) {
        int excl = g_ptr[i] - g_cnt[i] + g_bexcl[i >> 10];
        g_ptr[i] = excl;
        g_cur[i] = excl;
        if (i == n - 1) g_ptr[n] = excl + g_cnt[i];
    }
}

__global__ void k_place(const void* __restrict__ ei,
                        const float* __restrict__ ew, int e) {
    int i = blockIdx.x * blockDim.x + threadIdx.x;
    if (i < e) {
        int r = load_edge_idx(ei, (size_t)i);
        int c = load_edge_idx(ei, (size_t)e + i);
        float nm = g_dinv[r] * ew[i] * g_dinv[c];
        int pos = atomicAdd(&g_cur[c], 1);
        g_srt[pos] = make_int2(r, __float_as_int(nm));
    }
}

// ======== GEMM1 (mma.sync bf16x3 split): h = x@W1 ; out1 = h*dinv^2 ========
// block: 256 thr (8 warps), tile 128 rows x 128 cols, K chunked 2x64.
// smem (u32 words, stride 36/row): As_hi As_lo (128x36 each), Bs_hi Bs_lo.
#define SA 36
__global__ __launch_bounds__(256) void k_gemm1(const float* __restrict__ x,
                                               const float* __restrict__ W1,
                                               int M) {
    extern __shared__ uint32_t dsm1[];
    uint32_t* As_hi = dsm1;              // 128*36 = 4608
    uint32_t* As_lo = dsm1 + 4608;
    uint32_t* Bs_hi = dsm1 + 9216;
    uint32_t* Bs_lo = dsm1 + 13824;      // total 18432 u32 = 72KB

    const int tid  = threadIdx.x;
    const int wid  = tid >> 5;
    const int lane = tid & 31;
    const int g    = lane >> 2;
    const int t    = lane & 3;
    const int rowbase = blockIdx.x * 128;
    const int wrow = wid * 16;

    float c[16][4];
#pragma unroll
    for (int nt = 0; nt < 16; nt++)
#pragma unroll
        for (int j = 0; j < 4; j++) c[nt][j] = 0.f;

    for (int ch = 0; ch < 2; ch++) {
        const int kb = ch * 64;
        // --- stage A: 128 rows x 64 k fp32 -> hi/lo bf16 pairs ---
#pragma unroll
        for (int i = 0; i < 8; i++) {
            int lin = tid + i * 256;       // 2048 float4
            int row = lin >> 4;
            int kq  = lin & 15;            // k0 = kq*4
            int grow = rowbase + row;
            float4 f = make_float4(0.f, 0.f, 0.f, 0.f);
            if (grow < M)
                f = *(const float4*)(x + (size_t)grow * 128 + kb + kq * 4);
            uint32_t h0, l0, h1, l1;
            split_pair(f.x, f.y, h0, l0);
            split_pair(f.z, f.w, h1, l1);
            int w = row * SA + kq * 2;
            As_hi[w] = h0; As_hi[w + 1] = h1;
            As_lo[w] = l0; As_lo[w + 1] = l1;
        }
        // --- stage B: W1[kb+2kp..+1][n] -> Bs[n][kp] packed k-pairs ---
#pragma unroll
        for (int i = 0; i < 16; i++) {
            int lin = tid + i * 256;       // 4096 pairs = 32 kp x 128 n
            int kp = lin >> 7;
            int n  = lin & 127;
            float w0 = W1[(size_t)(kb + 2 * kp) * 128 + n];
            float w1 = W1[(size_t)(kb + 2 * kp + 1) * 128 + n];
            uint32_t h, l;
            split_pair(w0, w1, h, l);
            Bs_hi[n * SA + kp] = h;
            Bs_lo[n * SA + kp] = l;
        }
        __syncthreads();

#pragma unroll
        for (int ks = 0; ks < 4; ks++) {
            int abase = (wrow + g) * SA + ks * 8 + t;
            uint32_t ah0 = As_hi[abase],            ah1 = As_hi[abase + 8 * SA];
            uint32_t ah2 = As_hi[abase + 4],        ah3 = As_hi[abase + 8 * SA + 4];
            uint32_t al0 = As_lo[abase],            al1 = As_lo[abase + 8 * SA];
            uint32_t al2 = As_lo[abase + 4],        al3 = As_lo[abase + 8 * SA + 4];
#pragma unroll
            for (int nt = 0; nt < 16; nt++) {
                int bbase = (nt * 8 + g) * SA + ks * 8 + t;
                uint32_t bh0 = Bs_hi[bbase], bh1 = Bs_hi[bbase + 4];
                uint32_t bl0 = Bs_lo[bbase], bl1 = Bs_lo[bbase + 4];
                MMA_BF16(c[nt], ah0, ah1, ah2, ah3, bh0, bh1);
                MMA_BF16(c[nt], ah0, ah1, ah2, ah3, bl0, bl1);
                MMA_BF16(c[nt], al0, al1, al2, al3, bh0, bh1);
            }
        }
        __syncthreads();
    }

    // --- epilogue ---
    int row0 = rowbase + wrow + g;
    int row1 = row0 + 8;
    float s0 = 0.f, s1 = 0.f;
    if (row0 < M) { s0 = g_dinv[row0]; s0 *= s0; }
    if (row1 < M) { s1 = g_dinv[row1]; s1 *= s1; }
#pragma unroll
    for (int nt = 0; nt < 16; nt++) {
        int n = nt * 8 + 2 * t;
        if (row0 < M) {
            float2 v = make_float2(c[nt][0], c[nt][1]);
            *(float2*)(g_h    + (size_t)row0 * 128 + n) = v;
            *(float2*)(g_out1 + (size_t)row0 * 128 + n) =
                make_float2(v.x * s0, v.y * s0);
        }
        if (row1 < M) {
            float2 v = make_float2(c[nt][2], c[nt][3]);
            *(float2*)(g_h    + (size_t)row1 * 128 + n) = v;
            *(float2*)(g_out1 + (size_t)row1 * 128 + n) =
                make_float2(v.x * s1, v.y * s1);
        }
    }
}

// ---------------- agg layer 1: warp per destination node (128 feats) -------
__global__ __launch_bounds__(256) void k_agg1(int n) {
    int c = blockIdx.x * 8 + (threadIdx.x >> 5);
    if (c >= n) return;
    int lane = threadIdx.x & 31;
    int beg = g_ptr[c], end = g_ptr[c + 1];
    float4 acc = make_float4(0.f, 0.f, 0.f, 0.f);
    for (int e = beg; e < end; e++) {
        int2  en = g_srt[e];
        float nm = __int_as_float(en.y);
        float4 v = *(const float4*)(g_h + (size_t)en.x * 128 + lane * 4);
        acc.x = fmaf(v.x, nm, acc.x);
        acc.y = fmaf(v.y, nm, acc.y);
        acc.z = fmaf(v.z, nm, acc.z);
        acc.w = fmaf(v.w, nm, acc.w);
    }
    float* op = g_out1 + (size_t)c * 128 + lane * 4;
    float4 cur = *(float4*)op;
    cur.x += acc.x; cur.y += acc.y; cur.z += acc.z; cur.w += acc.w;
    *(float4*)op = cur;
}

// ======== GEMM2 (mma.sync bf16x3): t = relu(out1+b1)@W2 ; out=b2+t*dinv^2 ==
// block: 256 thr, tile 128 rows x 64 cols, K chunked 2x64.
__global__ __launch_bounds__(256) void k_gemm2(const float* __restrict__ W2,
                                               const float* __restrict__ b1,
                                               const float* __restrict__ b2,
                                               float* __restrict__ out, int M) {
    extern __shared__ uint32_t dsm2[];
    uint32_t* As_hi = dsm2;              // 4608
    uint32_t* As_lo = dsm2 + 4608;
    uint32_t* Bs_hi = dsm2 + 9216;       // 64*36 = 2304
    uint32_t* Bs_lo = dsm2 + 11520;      // total 13824 u32 = 54KB

    const int tid  = threadIdx.x;
    const int wid  = tid >> 5;
    const int lane = tid & 31;
    const int g    = lane >> 2;
    const int t    = lane & 3;
    const int rowbase = blockIdx.x * 128;
    const int wrow = wid * 16;

    float c[8][4];
#pragma unroll
    for (int nt = 0; nt < 8; nt++)
#pragma unroll
        for (int j = 0; j < 4; j++) c[nt][j] = 0.f;

    for (int ch = 0; ch < 2; ch++) {
        const int kb = ch * 64;
        // --- stage A with fused bias+relu ---
#pragma unroll
        for (int i = 0; i < 8; i++) {
            int lin = tid + i * 256;
            int row = lin >> 4;
            int kq  = lin & 15;
            int grow = rowbase + row;
            float4 f = make_float4(0.f, 0.f, 0.f, 0.f);
            if (grow < M) {
                int k0 = kb + kq * 4;
                f = *(const float4*)(g_out1 + (size_t)grow * 128 + k0);
                f.x = fmaxf(f.x + __ldg(b1 + k0 + 0), 0.f);
                f.y = fmaxf(f.y + __ldg(b1 + k0 + 1), 0.f);
                f.z = fmaxf(f.z + __ldg(b1 + k0 + 2), 0.f);
                f.w = fmaxf(f.w + __ldg(b1 + k0 + 3), 0.f);
            }
            uint32_t h0, l0, h1, l1;
            split_pair(f.x, f.y, h0, l0);
            split_pair(f.z, f.w, h1, l1);
            int w = row * SA + kq * 2;
            As_hi[w] = h0; As_hi[w + 1] = h1;
            As_lo[w] = l0; As_lo[w + 1] = l1;
        }
        // --- stage B: W2[kb+2kp..+1][n] ---
#pragma unroll
        for (int i = 0; i < 8; i++) {
            int lin = tid + i * 256;       // 2048 pairs = 32 kp x 64 n
            int kp = lin >> 6;
            int n  = lin & 63;
            float w0 = W2[(size_t)(kb + 2 * kp) * 64 + n];
            float w1 = W2[(size_t)(kb + 2 * kp + 1) * 64 + n];
            uint32_t h, l;
            split_pair(w0, w1, h, l);
            Bs_hi[n * SA + kp] = h;
            Bs_lo[n * SA + kp] = l;
        }
        __syncthreads();

#pragma unroll
        for (int ks = 0; ks < 4; ks++) {
            int abase = (wrow + g) * SA + ks * 8 + t;
            uint32_t ah0 = As_hi[abase],            ah1 = As_hi[abase + 8 * SA];
            uint32_t ah2 = As_hi[abase + 4],        ah3 = As_hi[abase + 8 * SA + 4];
            uint32_t al0 = As_lo[abase],            al1 = As_lo[abase + 8 * SA];
            uint32_t al2 = As_lo[abase + 4],        al3 = As_lo[abase + 8 * SA + 4];
#pragma unroll
            for (int nt = 0; nt < 8; nt++) {
                int bbase = (nt * 8 + g) * SA + ks * 8 + t;
                uint32_t bh0 = Bs_hi[bbase], bh1 = Bs_hi[bbase + 4];
                uint32_t bl0 = Bs_lo[bbase], bl1 = Bs_lo[bbase + 4];
                MMA_BF16(c[nt], ah0, ah1, ah2, ah3, bh0, bh1);
                MMA_BF16(c[nt], ah0, ah1, ah2, ah3, bl0, bl1);
                MMA_BF16(c[nt], al0, al1, al2, al3, bh0, bh1);
            }
        }
        __syncthreads();
    }

    // --- epilogue ---
    int row0 = rowbase + wrow + g;
    int row1 = row0 + 8;
    float s0 = 0.f, s1 = 0.f;
    if (row0 < M) { s0 = g_dinv[row0]; s0 *= s0; }
    if (row1 < M) { s1 = g_dinv[row1]; s1 *= s1; }
#pragma unroll
    for (int nt = 0; nt < 8; nt++) {
        int n = nt * 8 + 2 * t;
        float bz0 = __ldg(b2 + n), bz1 = __ldg(b2 + n + 1);
        if (row0 < M) {
            float2 v = make_float2(c[nt][0], c[nt][1]);
            *(float2*)(g_t + (size_t)row0 * 64 + n) = v;
            *(float2*)(out + (size_t)row0 * 64 + n) =
                make_float2(bz0 + v.x * s0, bz1 + v.y * s0);
        }
        if (row1 < M) {
            float2 v = make_float2(c[nt][2], c[nt][3]);
            *(float2*)(g_t + (size_t)row1 * 64 + n) = v;
            *(float2*)(out + (size_t)row1 * 64 + n) =
                make_float2(bz0 + v.x * s1, bz1 + v.y * s1);
        }
    }
}

// ---------------- agg layer 2: warp per destination node (64 feats) --------
__global__ __launch_bounds__(256) void k_agg2(float* __restrict__ out, int n) {
    int c = blockIdx.x * 8 + (threadIdx.x >> 5);
    if (c >= n) return;
    int lane = threadIdx.x & 31;
    int beg = g_ptr[c], end = g_ptr[c + 1];
    float2 acc = make_float2(0.f, 0.f);
    for (int e = beg; e < end; e++) {
        int2  en = g_srt[e];
        float nm = __int_as_float(en.y);
        float2 v = *(const float2*)(g_t + (size_t)en.x * 64 + lane * 2);
        acc.x = fmaf(v.x, nm, acc.x);
        acc.y = fmaf(v.y, nm, acc.y);
    }
    float* op = out + (size_t)c * 64 + lane * 2;
    float2 cur = *(float2*)op;
    cur.x += acc.x; cur.y += acc.y;
    *(float2*)op = cur;
}

// ---------------- entry ----------------------------------------------------
extern "C" void kernel_launch(void* const* d_in, const int* in_sizes, int n_in,
                              void* d_out, int out_size) {
    const float* x  = (const float*)d_in[0];
    const void*  ei = d_in[1];
    const float* ew = (const float*)d_in[2];
    const float* W1 = (const float*)d_in[3];
    const float* b1 = (const float*)d_in[4];
    const float* W2 = (const float*)d_in[5];
    const float* b2 = (const float*)d_in[6];
    float* out = (float*)d_out;

    int N = in_sizes[0] / F_IN;     // 50000
    int E = in_sizes[2];            // 800000
    int nScanBlocks = (N + 1023) / 1024;
    int nTiles = (N + 127) / 128;
    const int G1_SMEM = 18432 * 4;  // 73728 B
    const int G2_SMEM = 13824 * 4;  // 55296 B

    cudaFuncSetAttribute(k_gemm1, cudaFuncAttributeMaxDynamicSharedMemorySize,
                         G1_SMEM);
    cudaFuncSetAttribute(k_gemm2, cudaFuncAttributeMaxDynamicSharedMemorySize,
                         G2_SMEM);

    k_prep0   <<<(N + 255) / 256, 256>>>((const int*)ei, N);        // 0
    k_deg_hist<<<(E + 255) / 256, 256>>>(ei, ew, E);                // 1
    k_dinv    <<<(N + 255) / 256, 256>>>(N);                        // 2
    k_gemm1   <<<nTiles, 256, G1_SMEM>>>(x, W1, N);                 // 3 (profiled)
    k_scanA   <<<nScanBlocks, 1024>>>(N);                           // 4
    k_scanB   <<<1, 64>>>(nScanBlocks);                             // 5
    k_scanC   <<<(N + 255) / 256, 256>>>(N);                        // 6
    k_place   <<<(E + 255) / 256, 256>>>(ei, ew, E);                // 7
    k_agg1    <<<(N + 7) / 8, 256>>>(N);                            // 8
    k_gemm2   <<<nTiles, 256, G2_SMEM>>>(W2, b1, b2, out, N);       // 9
    k_agg2    <<<(N + 7) / 8, 256>>>(out, N);                       // 10
}

// round 7
// speedup vs baseline: 2.6314x; 1.1466x over previous
#include <cuda_runtime.h>
#include <cuda_bf16.h>
#include <cstdint>

#define N_NODES_MAX 50000
#define E_MAX       800000
#define F_IN  128
#define F_HID 128
#define F_OUT 64

// ---------------- scratch (device globals; no allocation allowed) ----------
__device__ float g_deg  [N_NODES_MAX];
__device__ float g_dinv [N_NODES_MAX];
__device__ int   g_cnt  [N_NODES_MAX];
__device__ int   g_ptr  [N_NODES_MAX + 1];
__device__ int   g_cur  [N_NODES_MAX];
__device__ int   g_bsum [64];
__device__ int   g_bexcl[64];
__device__ int2  g_srt  [E_MAX];                       // (row, norm-as-int)
__device__ float g_h   [(size_t)N_NODES_MAX * F_IN];   // x @ W1
__device__ float g_out1[(size_t)N_NODES_MAX * F_HID];  // layer-1 accum
__device__ float g_t   [(size_t)N_NODES_MAX * F_OUT];  // relu(h1) @ W2
__device__ int   g_is64;
// pre-split weights, transposed [n][k], bf16 hi/lo
__device__ __nv_bfloat16 g_w1t_hi[128 * 128];
__device__ __nv_bfloat16 g_w1t_lo[128 * 128];
__device__ __nv_bfloat16 g_w2t_hi[64 * 128];
__device__ __nv_bfloat16 g_w2t_lo[64 * 128];

// ---------------- helpers --------------------------------------------------
__device__ __forceinline__ int load_edge_idx(const void* ei, size_t pos) {
    if (g_is64) return (int)((const long long*)ei)[pos];
    return ((const int*)ei)[pos];
}

__device__ __forceinline__ uint32_t smem_u32(const void* p) {
    uint32_t a;
    asm("{ .reg .u64 t; cvta.to.shared.u64 t, %1; cvt.u32.u64 %0, t; }"
        : "=r"(a) : "l"(p));
    return a;
}

// split a pair of floats into packed bf16x2 (hi) and bf16x2 (residual lo)
__device__ __forceinline__ void split_pair(float a, float b,
                                           uint32_t& hi, uint32_t& lo) {
    __nv_bfloat16 ha = __float2bfloat16(a);
    __nv_bfloat16 hb = __float2bfloat16(b);
    float la = a - __bfloat162float(ha);
    float lb = b - __bfloat162float(hb);
    __nv_bfloat162 hp; hp.x = ha; hp.y = hb;
    __nv_bfloat162 lp; lp.x = __float2bfloat16(la); lp.y = __float2bfloat16(lb);
    hi = *reinterpret_cast<uint32_t*>(&hp);
    lo = *reinterpret_cast<uint32_t*>(&lp);
}

#define MMA_BF16(c, a0, a1, a2, a3, b0, b1)                                    \
    asm volatile("mma.sync.aligned.m16n8k16.row.col.f32.bf16.bf16.f32 "        \
                 "{%0,%1,%2,%3}, {%4,%5,%6,%7}, {%8,%9}, {%0,%1,%2,%3};"       \
                 : "+f"((c)[0]), "+f"((c)[1]), "+f"((c)[2]), "+f"((c)[3])      \
                 : "r"(a0), "r"(a1), "r"(a2), "r"(a3), "r"(b0), "r"(b1))

__device__ __forceinline__ void ldsm4(uint32_t& r0, uint32_t& r1,
                                      uint32_t& r2, uint32_t& r3,
                                      uint32_t addr) {
    asm volatile("ldmatrix.sync.aligned.m8n8.x4.shared.b16 {%0,%1,%2,%3}, [%4];"
                 : "=r"(r0), "=r"(r1), "=r"(r2), "=r"(r3) : "r"(addr));
}

// ---------------- prep0: deg/cnt init + dtype detect + W pre-split ---------
__global__ void k_prep0(const int* __restrict__ ei32,
                        const float* __restrict__ W1,
                        const float* __restrict__ W2, int n) {
    int i = blockIdx.x * blockDim.x + threadIdx.x;
    if (i < n) { g_deg[i] = 1.0f; g_cnt[i] = 0; }
    if (blockIdx.x == 0 && threadIdx.x < 32) {
        int v = ei32[threadIdx.x * 2 + 1] | ei32[64 + threadIdx.x * 2 + 1];
        unsigned m = __ballot_sync(0xffffffffu, v != 0);
        if (threadIdx.x == 0) g_is64 = (m == 0u);
    }
    if (i < 128 * 128) {                       // W1 split, transposed
        int k = i >> 7, nn = i & 127;
        float w = W1[i];
        __nv_bfloat16 hb = __float2bfloat16(w);
        g_w1t_hi[nn * 128 + k] = hb;
        g_w1t_lo[nn * 128 + k] = __float2bfloat16(w - __bfloat162float(hb));
    } else if (i < 128 * 128 + 128 * 64) {     // W2 split, transposed
        int r = i - 128 * 128;
        int k = r >> 6, nn = r & 63;
        float w = W2[r];
        __nv_bfloat16 hb = __float2bfloat16(w);
        g_w2t_hi[nn * 128 + k] = hb;
        g_w2t_lo[nn * 128 + k] = __float2bfloat16(w - __bfloat162float(hb));
    }
}

__global__ void k_deg_hist(const void* __restrict__ ei,
                           const float* __restrict__ ew, int e) {
    int i = blockIdx.x * blockDim.x + threadIdx.x;
    if (i < e) {
        int c = load_edge_idx(ei, (size_t)e + i);
        atomicAdd(&g_deg[c], ew[i]);
        atomicAdd(&g_cnt[c], 1);
    }
}

__global__ void k_dinv(int n) {
    int i = blockIdx.x * blockDim.x + threadIdx.x;
    if (i < n) {
        float d = g_deg[i];
        g_dinv[i] = (d > 0.f) ? rsqrtf(d) : 0.f;
    }
}

__global__ __launch_bounds__(1024) void k_scanA(int n) {
    __shared__ int s[1024];
    int i = blockIdx.x * 1024 + threadIdx.x;
    int v = (i < n) ? g_cnt[i] : 0;
    s[threadIdx.x] = v;
    __syncthreads();
#pragma unroll
    for (int off = 1; off < 1024; off <<= 1) {
        int t = (threadIdx.x >= off) ? s[threadIdx.x - off] : 0;
        __syncthreads();
        s[threadIdx.x] += t;
        __syncthreads();
    }
    if (i < n) g_ptr[i] = s[threadIdx.x];
    if (threadIdx.x == 1023) g_bsum[blockIdx.x] = s[1023];
}

__global__ void k_scanB(int nb) {
    __shared__ int s[64];
    int v = (threadIdx.x < nb) ? g_bsum[threadIdx.x] : 0;
    s[threadIdx.x] = v;
    __syncthreads();
#pragma unroll
    for (int off = 1; off < 64; off <<= 1) {
        int t = (threadIdx.x >= off) ? s[threadIdx.x - off] : 0;
        __syncthreads();
        s[threadIdx.x] += t;
        __syncthreads();
    }
    g_bexcl[threadIdx.x] = s[threadIdx.x] - v;
}

__global__ void k_scanC(int n) {
    int i = blockIdx.x * blockDim.x + threadIdx.x;
    if (i < n) {
        int excl = g_ptr[i] - g_cnt[i] + g_bexcl[i >> 10];
        g_ptr[i] = excl;
        g_cur[i] = excl;
        if (i == n - 1) g_ptr[n] = excl + g_cnt[i];
    }
}

__global__ void k_place(const void* __restrict__ ei,
                        const float* __restrict__ ew, int e) {
    int i = blockIdx.x * blockDim.x + threadIdx.x;
    if (i < e) {
        int r = load_edge_idx(ei, (size_t)i);
        int c = load_edge_idx(ei, (size_t)e + i);
        float nm = g_dinv[r] * ew[i] * g_dinv[c];
        int pos = atomicAdd(&g_cur[c], 1);
        g_srt[pos] = make_int2(r, __float_as_int(nm));
    }
}

// smem row stride: 36 u32 (144 B) -> 4r mod 32 bank pattern, conflict-free
#define SA 36

// ======== GEMM1 (mma.sync + ldmatrix): h = x@W1 ; out1 = h*dinv^2 ==========
// block 256 thr (8 warps), tile 128x128, K chunked 2x64.
__global__ __launch_bounds__(256) void k_gemm1(const float* __restrict__ x,
                                               int M) {
    extern __shared__ uint32_t dsm1[];
    uint32_t* As_hi = dsm1;              // 128*36
    uint32_t* As_lo = dsm1 + 4608;
    uint32_t* Bs_hi = dsm1 + 9216;
    uint32_t* Bs_lo = dsm1 + 13824;      // total 18432 u32 = 72KB

    const int tid  = threadIdx.x;
    const int wid  = tid >> 5;
    const int lane = tid & 31;
    const int g    = lane >> 2;
    const int t    = lane & 3;
    const int rowbase = blockIdx.x * 128;
    const int wrow = wid * 16;

    // ldmatrix per-lane base addresses
    const int lr = lane & 7, lm = lane >> 3;
    const uint32_t a_hi_base = smem_u32(As_hi) +
        (uint32_t)(wrow + lr + ((lm & 1) << 3)) * 144 + ((lm >> 1) << 4);
    const uint32_t a_lo_base = a_hi_base + 4608u * 4u;
    const uint32_t b_hi_base = smem_u32(Bs_hi) +
        (uint32_t)(lr + ((lm >> 1) << 3)) * 144 + ((lm & 1) << 4);
    const uint32_t b_lo_base = b_hi_base + 4608u * 4u;

    float c[16][4];
#pragma unroll
    for (int nt = 0; nt < 16; nt++)
#pragma unroll
        for (int j = 0; j < 4; j++) c[nt][j] = 0.f;

    for (int ch = 0; ch < 2; ch++) {
        const int kb = ch * 64;
        // --- stage A: split fp32 -> hi/lo bf16 pairs (inline) ---
#pragma unroll
        for (int i = 0; i < 8; i++) {
            int lin = tid + i * 256;       // 2048 float4
            int row = lin >> 4;
            int kq  = lin & 15;            // k0 = kq*4
            int grow = rowbase + row;
            float4 f = make_float4(0.f, 0.f, 0.f, 0.f);
            if (grow < M)
                f = *(const float4*)(x + (size_t)grow * 128 + kb + kq * 4);
            uint32_t h0, l0, h1, l1;
            split_pair(f.x, f.y, h0, l0);
            split_pair(f.z, f.w, h1, l1);
            int w = row * SA + kq * 2;
            As_hi[w] = h0; As_hi[w + 1] = h1;
            As_lo[w] = l0; As_lo[w + 1] = l1;
        }
        // --- stage B: copy pre-split w1t [n][k] chunk (uint4) ---
#pragma unroll
        for (int i = 0; i < 4; i++) {
            int lin = tid + i * 256;       // 1024 uint4 per array
            int n = lin >> 3;
            int q = lin & 7;               // 8 bf16 per uint4
            uint4 vh = *(const uint4*)(g_w1t_hi + (size_t)n * 128 + kb + q * 8);
            uint4 vl = *(const uint4*)(g_w1t_lo + (size_t)n * 128 + kb + q * 8);
            *(uint4*)&Bs_hi[n * SA + q * 4] = vh;
            *(uint4*)&Bs_lo[n * SA + q * 4] = vl;
        }
        __syncthreads();

#pragma unroll
        for (int ks = 0; ks < 4; ks++) {
            const uint32_t ko = ks * 32;   // 16 bf16 = 32 B
            uint32_t ah0, ah1, ah2, ah3, al0, al1, al2, al3;
            ldsm4(ah0, ah1, ah2, ah3, a_hi_base + ko);
            ldsm4(al0, al1, al2, al3, a_lo_base + ko);
#pragma unroll
            for (int p = 0; p < 8; p++) {
                uint32_t bh0, bh1, bh2, bh3, bl0, bl1, bl2, bl3;
                ldsm4(bh0, bh1, bh2, bh3, b_hi_base + p * 2304u + ko);
                ldsm4(bl0, bl1, bl2, bl3, b_lo_base + p * 2304u + ko);
                MMA_BF16(c[2 * p],     ah0, ah1, ah2, ah3, bh0, bh1);
                MMA_BF16(c[2 * p],     ah0, ah1, ah2, ah3, bl0, bl1);
                MMA_BF16(c[2 * p],     al0, al1, al2, al3, bh0, bh1);
                MMA_BF16(c[2 * p + 1], ah0, ah1, ah2, ah3, bh2, bh3);
                MMA_BF16(c[2 * p + 1], ah0, ah1, ah2, ah3, bl2, bl3);
                MMA_BF16(c[2 * p + 1], al0, al1, al2, al3, bh2, bh3);
            }
        }
        __syncthreads();
    }

    // --- epilogue ---
    int row0 = rowbase + wrow + g;
    int row1 = row0 + 8;
    float s0 = 0.f, s1 = 0.f;
    if (row0 < M) { s0 = g_dinv[row0]; s0 *= s0; }
    if (row1 < M) { s1 = g_dinv[row1]; s1 *= s1; }
#pragma unroll
    for (int nt = 0; nt < 16; nt++) {
        int n = nt * 8 + 2 * t;
        if (row0 < M) {
            float2 v = make_float2(c[nt][0], c[nt][1]);
            *(float2*)(g_h    + (size_t)row0 * 128 + n) = v;
            *(float2*)(g_out1 + (size_t)row0 * 128 + n) =
                make_float2(v.x * s0, v.y * s0);
        }
        if (row1 < M) {
            float2 v = make_float2(c[nt][2], c[nt][3]);
            *(float2*)(g_h    + (size_t)row1 * 128 + n) = v;
            *(float2*)(g_out1 + (size_t)row1 * 128 + n) =
                make_float2(v.x * s1, v.y * s1);
        }
    }
}

// ---------------- agg layer 1: warp per destination node (128 feats) -------
__global__ __launch_bounds__(256) void k_agg1(int n) {
    int c = blockIdx.x * 8 + (threadIdx.x >> 5);
    if (c >= n) return;
    int lane = threadIdx.x & 31;
    int beg = g_ptr[c], end = g_ptr[c + 1];
    float4 acc = make_float4(0.f, 0.f, 0.f, 0.f);
    for (int e = beg; e < end; e++) {
        int2  en = g_srt[e];
        float nm = __int_as_float(en.y);
        float4 v = *(const float4*)(g_h + (size_t)en.x * 128 + lane * 4);
        acc.x = fmaf(v.x, nm, acc.x);
        acc.y = fmaf(v.y, nm, acc.y);
        acc.z = fmaf(v.z, nm, acc.z);
        acc.w = fmaf(v.w, nm, acc.w);
    }
    float* op = g_out1 + (size_t)c * 128 + lane * 4;
    float4 cur = *(float4*)op;
    cur.x += acc.x; cur.y += acc.y; cur.z += acc.z; cur.w += acc.w;
    *(float4*)op = cur;
}

// ======== GEMM2 (mma.sync + ldmatrix): t = relu(out1+b1)@W2 ================
// block 256 thr, tile 128x64, K chunked 2x64.
__global__ __launch_bounds__(256) void k_gemm2(const float* __restrict__ b1,
                                               const float* __restrict__ b2,
                                               float* __restrict__ out, int M) {
    extern __shared__ uint32_t dsm2[];
    uint32_t* As_hi = dsm2;              // 4608
    uint32_t* As_lo = dsm2 + 4608;
    uint32_t* Bs_hi = dsm2 + 9216;       // 64*36 = 2304
    uint32_t* Bs_lo = dsm2 + 11520;      // total 13824 u32 = 54KB

    const int tid  = threadIdx.x;
    const int wid  = tid >> 5;
    const int lane = tid & 31;
    const int g    = lane >> 2;
    const int t    = lane & 3;
    const int rowbase = blockIdx.x * 128;
    const int wrow = wid * 16;

    const int lr = lane & 7, lm = lane >> 3;
    const uint32_t a_hi_base = smem_u32(As_hi) +
        (uint32_t)(wrow + lr + ((lm & 1) << 3)) * 144 + ((lm >> 1) << 4);
    const uint32_t a_lo_base = a_hi_base + 4608u * 4u;
    const uint32_t b_hi_base = smem_u32(Bs_hi) +
        (uint32_t)(lr + ((lm >> 1) << 3)) * 144 + ((lm & 1) << 4);
    const uint32_t b_lo_base = b_hi_base + 2304u * 4u;

    float c[8][4];
#pragma unroll
    for (int nt = 0; nt < 8; nt++)
#pragma unroll
        for (int j = 0; j < 4; j++) c[nt][j] = 0.f;

    for (int ch = 0; ch < 2; ch++) {
        const int kb = ch * 64;
        // --- stage A with fused bias+relu and split ---
#pragma unroll
        for (int i = 0; i < 8; i++) {
            int lin = tid + i * 256;
            int row = lin >> 4;
            int kq  = lin & 15;
            int grow = rowbase + row;
            float4 f = make_float4(0.f, 0.f, 0.f, 0.f);
            if (grow < M) {
                int k0 = kb + kq * 4;
                f = *(const float4*)(g_out1 + (size_t)grow * 128 + k0);
                f.x = fmaxf(f.x + __ldg(b1 + k0 + 0), 0.f);
                f.y = fmaxf(f.y + __ldg(b1 + k0 + 1), 0.f);
                f.z = fmaxf(f.z + __ldg(b1 + k0 + 2), 0.f);
                f.w = fmaxf(f.w + __ldg(b1 + k0 + 3), 0.f);
            }
            uint32_t h0, l0, h1, l1;
            split_pair(f.x, f.y, h0, l0);
            split_pair(f.z, f.w, h1, l1);
            int w = row * SA + kq * 2;
            As_hi[w] = h0; As_hi[w + 1] = h1;
            As_lo[w] = l0; As_lo[w + 1] = l1;
        }
        // --- stage B: copy pre-split w2t chunk ---
#pragma unroll
        for (int i = 0; i < 2; i++) {
            int lin = tid + i * 256;       // 512 uint4 per array
            int n = lin >> 3;
            int q = lin & 7;
            uint4 vh = *(const uint4*)(g_w2t_hi + (size_t)n * 128 + kb + q * 8);
            uint4 vl = *(const uint4*)(g_w2t_lo + (size_t)n * 128 + kb + q * 8);
            *(uint4*)&Bs_hi[n * SA + q * 4] = vh;
            *(uint4*)&Bs_lo[n * SA + q * 4] = vl;
        }
        __syncthreads();

#pragma unroll
        for (int ks = 0; ks < 4; ks++) {
            const uint32_t ko = ks * 32;
            uint32_t ah0, ah1, ah2, ah3, al0, al1, al2, al3;
            ldsm4(ah0, ah1, ah2, ah3, a_hi_base + ko);
            ldsm4(al0, al1, al2, al3, a_lo_base + ko);
#pragma unroll
            for (int p = 0; p < 4; p++) {
                uint32_t bh0, bh1, bh2, bh3, bl0, bl1, bl2, bl3;
                ldsm4(bh0, bh1, bh2, bh3, b_hi_base + p * 2304u + ko);
                ldsm4(bl0, bl1, bl2, bl3, b_lo_base + p * 2304u + ko);
                MMA_BF16(c[2 * p],     ah0, ah1, ah2, ah3, bh0, bh1);
                MMA_BF16(c[2 * p],     ah0, ah1, ah2, ah3, bl0, bl1);
                MMA_BF16(c[2 * p],     al0, al1, al2, al3, bh0, bh1);
                MMA_BF16(c[2 * p + 1], ah0, ah1, ah2, ah3, bh2, bh3);
                MMA_BF16(c[2 * p + 1], ah0, ah1, ah2, ah3, bl2, bl3);
                MMA_BF16(c[2 * p + 1], al0, al1, al2, al3, bh2, bh3);
            }
        }
        __syncthreads();
    }

    // --- epilogue ---
    int row0 = rowbase + wrow + g;
    int row1 = row0 + 8;
    float s0 = 0.f, s1 = 0.f;
    if (row0 < M) { s0 = g_dinv[row0]; s0 *= s0; }
    if (row1 < M) { s1 = g_dinv[row1]; s1 *= s1; }
#pragma unroll
    for (int nt = 0; nt < 8; nt++) {
        int n = nt * 8 + 2 * t;
        float bz0 = __ldg(b2 + n), bz1 = __ldg(b2 + n + 1);
        if (row0 < M) {
            float2 v = make_float2(c[nt][0], c[nt][1]);
            *(float2*)(g_t + (size_t)row0 * 64 + n) = v;
            *(float2*)(out + (size_t)row0 * 64 + n) =
                make_float2(bz0 + v.x * s0, bz1 + v.y * s0);
        }
        if (row1 < M) {
            float2 v = make_float2(c[nt][2], c[nt][3]);
            *(float2*)(g_t + (size_t)row1 * 64 + n) = v;
            *(float2*)(out + (size_t)row1 * 64 + n) =
                make_float2(bz0 + v.x * s1, bz1 + v.y * s1);
        }
    }
}

// ---------------- agg layer 2: warp per destination node (64 feats) --------
__global__ __launch_bounds__(256) void k_agg2(float* __restrict__ out, int n) {
    int c = blockIdx.x * 8 + (threadIdx.x >> 5);
    if (c >= n) return;
    int lane = threadIdx.x & 31;
    int beg = g_ptr[c], end = g_ptr[c + 1];
    float2 acc = make_float2(0.f, 0.f);
    for (int e = beg; e < end; e++) {
        int2  en = g_srt[e];
        float nm = __int_as_float(en.y);
        float2 v = *(const float2*)(g_t + (size_t)en.x * 64 + lane * 2);
        acc.x = fmaf(v.x, nm, acc.x);
        acc.y = fmaf(v.y, nm, acc.y);
    }
    float* op = out + (size_t)c * 64 + lane * 2;
    float2 cur = *(float2*)op;
    cur.x += acc.x; cur.y += acc.y;
    *(float2*)op = cur;
}

// ---------------- entry ----------------------------------------------------
extern "C" void kernel_launch(void* const* d_in, const int* in_sizes, int n_in,
                              void* d_out, int out_size) {
    const float* x  = (const float*)d_in[0];
    const void*  ei = d_in[1];
    const float* ew = (const float*)d_in[2];
    const float* W1 = (const float*)d_in[3];
    const float* b1 = (const float*)d_in[4];
    const float* W2 = (const float*)d_in[5];
    const float* b2 = (const float*)d_in[6];
    float* out = (float*)d_out;

    int N = in_sizes[0] / F_IN;     // 50000
    int E = in_sizes[2];            // 800000
    int nScanBlocks = (N + 1023) / 1024;
    int nTiles = (N + 127) / 128;
    const int G1_SMEM = 18432 * 4;  // 73728 B
    const int G2_SMEM = 13824 * 4;  // 55296 B

    cudaFuncSetAttribute(k_gemm1, cudaFuncAttributeMaxDynamicSharedMemorySize,
                         G1_SMEM);
    cudaFuncSetAttribute(k_gemm2, cudaFuncAttributeMaxDynamicSharedMemorySize,
                         G2_SMEM);

    k_prep0   <<<(N + 255) / 256, 256>>>((const int*)ei, W1, W2, N);  // 0
    k_deg_hist<<<(E + 255) / 256, 256>>>(ei, ew, E);                  // 1
    k_dinv    <<<(N + 255) / 256, 256>>>(N);                          // 2
    k_gemm1   <<<nTiles, 256, G1_SMEM>>>(x, N);                       // 3 (profiled)
    k_scanA   <<<nScanBlocks, 1024>>>(N);                             // 4
    k_scanB   <<<1, 64>>>(nScanBlocks);                               // 5
    k_scanC   <<<(N + 255) / 256, 256>>>(N);                          // 6
    k_place   <<<(E + 255) / 256, 256>>>(ei, ew, E);                  // 7
    k_agg1    <<<(N + 7) / 8, 256>>>(N);                              // 8
    k_gemm2   <<<nTiles, 256, G2_SMEM>>>(b1, b2, out, N);             // 9
    k_agg2    <<<(N + 7) / 8, 256>>>(out, N);                         // 10
}

// round 8
// speedup vs baseline: 3.0759x; 1.1689x over previous
#include <cuda_runtime.h>
#include <cuda_bf16.h>
#include <cuda_fp16.h>
#include <cstdint>

#define N_NODES_MAX 50000
#define E_MAX       800000
#define F_IN  128
#define F_HID 128
#define F_OUT 64

// ---------------- scratch (device globals; no allocation allowed) ----------
__device__ float g_deg  [N_NODES_MAX];                 // zeroed after use (dinv)
__device__ float g_dinv [N_NODES_MAX];
__device__ int   g_cnt  [N_NODES_MAX];                 // zeroed after use (scanC)
__device__ int   g_ptr  [N_NODES_MAX + 1];
__device__ int   g_cur  [N_NODES_MAX];
__device__ int   g_bsum [64];
__device__ int   g_bexcl[64];
__device__ int2  g_srt  [E_MAX];                       // (row, norm-as-int)
__device__ __align__(16) __half g_h16[(size_t)N_NODES_MAX * F_IN];  // x@W1, fp16
__device__ float g_out1[(size_t)N_NODES_MAX * F_HID];  // layer-1 result (fp32)
__device__ __align__(16) __half g_t16[(size_t)N_NODES_MAX * F_OUT]; // relu@W2, fp16
__device__ int   g_is64;
// pre-split weights, transposed [n][k], bf16 hi/lo
__device__ __nv_bfloat16 g_w1t_hi[128 * 128];
__device__ __nv_bfloat16 g_w1t_lo[128 * 128];
__device__ __nv_bfloat16 g_w2t_hi[64 * 128];
__device__ __nv_bfloat16 g_w2t_lo[64 * 128];

// ---------------- helpers --------------------------------------------------
__device__ __forceinline__ int load_edge_idx(const void* ei, size_t pos) {
    if (g_is64) return (int)((const long long*)ei)[pos];
    return ((const int*)ei)[pos];
}

__device__ __forceinline__ uint32_t smem_u32(const void* p) {
    uint32_t a;
    asm("{ .reg .u64 t; cvta.to.shared.u64 t, %1; cvt.u32.u64 %0, t; }"
        : "=r"(a) : "l"(p));
    return a;
}

// split a pair of floats into packed bf16x2 (hi) and bf16x2 (residual lo)
__device__ __forceinline__ void split_pair(float a, float b,
                                           uint32_t& hi, uint32_t& lo) {
    __nv_bfloat16 ha = __float2bfloat16(a);
    __nv_bfloat16 hb = __float2bfloat16(b);
    float la = a - __bfloat162float(ha);
    float lb = b - __bfloat162float(hb);
    __nv_bfloat162 hp; hp.x = ha; hp.y = hb;
    __nv_bfloat162 lp; lp.x = __float2bfloat16(la); lp.y = __float2bfloat16(lb);
    hi = *reinterpret_cast<uint32_t*>(&hp);
    lo = *reinterpret_cast<uint32_t*>(&lp);
}

#define MMA_BF16(c, a0, a1, a2, a3, b0, b1)                                    \
    asm volatile("mma.sync.aligned.m16n8k16.row.col.f32.bf16.bf16.f32 "        \
                 "{%0,%1,%2,%3}, {%4,%5,%6,%7}, {%8,%9}, {%0,%1,%2,%3};"       \
                 : "+f"((c)[0]), "+f"((c)[1]), "+f"((c)[2]), "+f"((c)[3])      \
                 : "r"(a0), "r"(a1), "r"(a2), "r"(a3), "r"(b0), "r"(b1))

__device__ __forceinline__ void ldsm4(uint32_t& r0, uint32_t& r1,
                                      uint32_t& r2, uint32_t& r3,
                                      uint32_t addr) {
    asm volatile("ldmatrix.sync.aligned.m8n8.x4.shared.b16 {%0,%1,%2,%3}, [%4];"
                 : "=r"(r0), "=r"(r1), "=r"(r2), "=r"(r3) : "r"(addr));
}

// ---------------- prep0: dtype detect + W pre-split (small grid) ------------
__global__ void k_prep0(const int* __restrict__ ei32,
                        const float* __restrict__ W1,
                        const float* __restrict__ W2) {
    int i = blockIdx.x * blockDim.x + threadIdx.x;
    if (blockIdx.x == 0 && threadIdx.x < 32) {
        int v = ei32[threadIdx.x * 2 + 1] | ei32[64 + threadIdx.x * 2 + 1];
        unsigned m = __ballot_sync(0xffffffffu, v != 0);
        if (threadIdx.x == 0) g_is64 = (m == 0u);
    }
    if (i < 128 * 128) {                       // W1 split, transposed
        int k = i >> 7, nn = i & 127;
        float w = W1[i];
        __nv_bfloat16 hb = __float2bfloat16(w);
        g_w1t_hi[nn * 128 + k] = hb;
        g_w1t_lo[nn * 128 + k] = __float2bfloat16(w - __bfloat162float(hb));
    } else if (i < 128 * 128 + 128 * 64) {     // W2 split, transposed
        int r = i - 128 * 128;
        int k = r >> 6, nn = r & 63;
        float w = W2[r];
        __nv_bfloat16 hb = __float2bfloat16(w);
        g_w2t_hi[nn * 128 + k] = hb;
        g_w2t_lo[nn * 128 + k] = __float2bfloat16(w - __bfloat162float(hb));
    }
}

__global__ void k_deg_hist(const void* __restrict__ ei,
                           const float* __restrict__ ew, int e) {
    int i = blockIdx.x * blockDim.x + threadIdx.x;
    if (i < e) {
        int c = load_edge_idx(ei, (size_t)e + i);
        atomicAdd(&g_deg[c], ew[i]);
        atomicAdd(&g_cnt[c], 1);
    }
}

__global__ void k_dinv(int n) {
    int i = blockIdx.x * blockDim.x + threadIdx.x;
    if (i < n) {
        float d = g_deg[i] + 1.0f;     // self-loop weight folded here; d >= 1
        g_dinv[i] = rsqrtf(d);
        g_deg[i] = 0.f;                // reset for next graph replay
    }
}

__global__ __launch_bounds__(1024) void k_scanA(int n) {
    __shared__ int s[1024];
    int i = blockIdx.x * 1024 + threadIdx.x;
    int v = (i < n) ? g_cnt[i] : 0;
    s[threadIdx.x] = v;
    __syncthreads();
#pragma unroll
    for (int off = 1; off < 1024; off <<= 1) {
        int t = (threadIdx.x >= off) ? s[threadIdx.x - off] : 0;
        __syncthreads();
        s[threadIdx.x] += t;
        __syncthreads();
    }
    if (i < n) g_ptr[i] = s[threadIdx.x];
    if (threadIdx.x == 1023) g_bsum[blockIdx.x] = s[1023];
}

__global__ void k_scanB(int nb) {
    __shared__ int s[64];
    int v = (threadIdx.x < nb) ? g_bsum[threadIdx.x] : 0;
    s[threadIdx.x] = v;
    __syncthreads();
#pragma unroll
    for (int off = 1; off < 64; off <<= 1) {
        int t = (threadIdx.x >= off) ? s[threadIdx.x - off] : 0;
        __syncthreads();
        s[threadIdx.x] += t;
        __syncthreads();
    }
    g_bexcl[threadIdx.x] = s[threadIdx.x] - v;
}

__global__ void k_scanC(int n) {
    int i = blockIdx.x * blockDim.x + threadIdx.x;
    if (i < n) {
        int cnt = g_cnt[i];
        int excl = g_ptr[i] - cnt + g_bexcl[i >> 10];
        g_ptr[i] = excl;
        g_cur[i] = excl;
        g_cnt[i] = 0;                  // reset for next graph replay
        if (i == n - 1) g_ptr[n] = excl + cnt;
    }
}

__global__ void k_place(const void* __restrict__ ei,
                        const float* __restrict__ ew, int e) {
    int i = blockIdx.x * blockDim.x + threadIdx.x;
    if (i < e) {
        int r = load_edge_idx(ei, (size_t)i);
        int c = load_edge_idx(ei, (size_t)e + i);
        float nm = g_dinv[r] * ew[i] * g_dinv[c];
        int pos = atomicAdd(&g_cur[c], 1);
        g_srt[pos] = make_int2(r, __float_as_int(nm));
    }
}

// smem row stride: 36 u32 (144 B) -> conflict-free for LDSM and staging
#define SA 36

// ======== GEMM1 (mma.sync + ldmatrix): g_h16 = fp16(x @ W1) ================
// block 256 thr (8 warps), tile 128x128, K chunked 2x64.
__global__ __launch_bounds__(256) void k_gemm1(const float* __restrict__ x,
                                               int M) {
    extern __shared__ uint32_t dsm1[];
    uint32_t* As_hi = dsm1;              // 128*36
    uint32_t* As_lo = dsm1 + 4608;
    uint32_t* Bs_hi = dsm1 + 9216;
    uint32_t* Bs_lo = dsm1 + 13824;      // total 18432 u32 = 72KB

    const int tid  = threadIdx.x;
    const int wid  = tid >> 5;
    const int lane = tid & 31;
    const int g    = lane >> 2;
    const int t    = lane & 3;
    const int rowbase = blockIdx.x * 128;
    const int wrow = wid * 16;

    const int lr = lane & 7, lm = lane >> 3;
    const uint32_t a_hi_base = smem_u32(As_hi) +
        (uint32_t)(wrow + lr + ((lm & 1) << 3)) * 144 + ((lm >> 1) << 4);
    const uint32_t a_lo_base = a_hi_base + 4608u * 4u;
    const uint32_t b_hi_base = smem_u32(Bs_hi) +
        (uint32_t)(lr + ((lm >> 1) << 3)) * 144 + ((lm & 1) << 4);
    const uint32_t b_lo_base = b_hi_base + 4608u * 4u;

    float c[16][4];
#pragma unroll
    for (int nt = 0; nt < 16; nt++)
#pragma unroll
        for (int j = 0; j < 4; j++) c[nt][j] = 0.f;

    for (int ch = 0; ch < 2; ch++) {
        const int kb = ch * 64;
#pragma unroll
        for (int i = 0; i < 8; i++) {
            int lin = tid + i * 256;
            int row = lin >> 4;
            int kq  = lin & 15;
            int grow = rowbase + row;
            float4 f = make_float4(0.f, 0.f, 0.f, 0.f);
            if (grow < M)
                f = *(const float4*)(x + (size_t)grow * 128 + kb + kq * 4);
            uint32_t h0, l0, h1, l1;
            split_pair(f.x, f.y, h0, l0);
            split_pair(f.z, f.w, h1, l1);
            int w = row * SA + kq * 2;
            As_hi[w] = h0; As_hi[w + 1] = h1;
            As_lo[w] = l0; As_lo[w + 1] = l1;
        }
#pragma unroll
        for (int i = 0; i < 4; i++) {
            int lin = tid + i * 256;
            int n = lin >> 3;
            int q = lin & 7;
            uint4 vh = *(const uint4*)(g_w1t_hi + (size_t)n * 128 + kb + q * 8);
            uint4 vl = *(const uint4*)(g_w1t_lo + (size_t)n * 128 + kb + q * 8);
            *(uint4*)&Bs_hi[n * SA + q * 4] = vh;
            *(uint4*)&Bs_lo[n * SA + q * 4] = vl;
        }
        __syncthreads();

#pragma unroll
        for (int ks = 0; ks < 4; ks++) {
            const uint32_t ko = ks * 32;
            uint32_t ah0, ah1, ah2, ah3, al0, al1, al2, al3;
            ldsm4(ah0, ah1, ah2, ah3, a_hi_base + ko);
            ldsm4(al0, al1, al2, al3, a_lo_base + ko);
#pragma unroll
            for (int p = 0; p < 8; p++) {
                uint32_t bh0, bh1, bh2, bh3, bl0, bl1, bl2, bl3;
                ldsm4(bh0, bh1, bh2, bh3, b_hi_base + p * 2304u + ko);
                ldsm4(bl0, bl1, bl2, bl3, b_lo_base + p * 2304u + ko);
                MMA_BF16(c[2 * p],     ah0, ah1, ah2, ah3, bh0, bh1);
                MMA_BF16(c[2 * p],     ah0, ah1, ah2, ah3, bl0, bl1);
                MMA_BF16(c[2 * p],     al0, al1, al2, al3, bh0, bh1);
                MMA_BF16(c[2 * p + 1], ah0, ah1, ah2, ah3, bh2, bh3);
                MMA_BF16(c[2 * p + 1], ah0, ah1, ah2, ah3, bl2, bl3);
                MMA_BF16(c[2 * p + 1], al0, al1, al2, al3, bh2, bh3);
            }
        }
        __syncthreads();
    }

    // --- epilogue: fp16 payload only ---
    int row0 = rowbase + wrow + g;
    int row1 = row0 + 8;
#pragma unroll
    for (int nt = 0; nt < 16; nt++) {
        int n = nt * 8 + 2 * t;
        if (row0 < M) {
            __half2 v = __floats2half2_rn(c[nt][0], c[nt][1]);
            *(__half2*)(g_h16 + (size_t)row0 * 128 + n) = v;
        }
        if (row1 < M) {
            __half2 v = __floats2half2_rn(c[nt][2], c[nt][3]);
            *(__half2*)(g_h16 + (size_t)row1 * 128 + n) = v;
        }
    }
}

// ---- agg layer 1: out1[c] = sum nm*h16[src] + dinv^2*h16[c]  (fp32 acc) ----
__global__ __launch_bounds__(256) void k_agg1(int n) {
    int c = blockIdx.x * 8 + (threadIdx.x >> 5);
    if (c >= n) return;
    int lane = threadIdx.x & 31;
    int beg = g_ptr[c], end = g_ptr[c + 1];

    float sc = g_dinv[c]; sc = sc * sc;
    uint2 hv = *(const uint2*)(g_h16 + (size_t)c * 128 + lane * 4);
    float2 s0 = __half22float2(*(__half2*)&hv.x);
    float2 s1 = __half22float2(*(__half2*)&hv.y);
    float4 acc = make_float4(s0.x * sc, s0.y * sc, s1.x * sc, s1.y * sc);

    for (int e = beg; e < end; e++) {
        int2  en = g_srt[e];
        float nm = __int_as_float(en.y);
        uint2 v = *(const uint2*)(g_h16 + (size_t)en.x * 128 + lane * 4);
        float2 f0 = __half22float2(*(__half2*)&v.x);
        float2 f1 = __half22float2(*(__half2*)&v.y);
        acc.x = fmaf(f0.x, nm, acc.x);
        acc.y = fmaf(f0.y, nm, acc.y);
        acc.z = fmaf(f1.x, nm, acc.z);
        acc.w = fmaf(f1.y, nm, acc.w);
    }
    *(float4*)(g_out1 + (size_t)c * 128 + lane * 4) = acc;
}

// ======== GEMM2 (mma.sync + ldmatrix): g_t16 = fp16(relu(out1+b1) @ W2) ====
__global__ __launch_bounds__(256) void k_gemm2(const float* __restrict__ b1,
                                               int M) {
    extern __shared__ uint32_t dsm2[];
    uint32_t* As_hi = dsm2;
    uint32_t* As_lo = dsm2 + 4608;
    uint32_t* Bs_hi = dsm2 + 9216;
    uint32_t* Bs_lo = dsm2 + 11520;      // total 13824 u32 = 54KB

    const int tid  = threadIdx.x;
    const int wid  = tid >> 5;
    const int lane = tid & 31;
    const int g    = lane >> 2;
    const int t    = lane & 3;
    const int rowbase = blockIdx.x * 128;
    const int wrow = wid * 16;

    const int lr = lane & 7, lm = lane >> 3;
    const uint32_t a_hi_base = smem_u32(As_hi) +
        (uint32_t)(wrow + lr + ((lm & 1) << 3)) * 144 + ((lm >> 1) << 4);
    const uint32_t a_lo_base = a_hi_base + 4608u * 4u;
    const uint32_t b_hi_base = smem_u32(Bs_hi) +
        (uint32_t)(lr + ((lm >> 1) << 3)) * 144 + ((lm & 1) << 4);
    const uint32_t b_lo_base = b_hi_base + 2304u * 4u;

    float c[8][4];
#pragma unroll
    for (int nt = 0; nt < 8; nt++)
#pragma unroll
        for (int j = 0; j < 4; j++) c[nt][j] = 0.f;

    for (int ch = 0; ch < 2; ch++) {
        const int kb = ch * 64;
#pragma unroll
        for (int i = 0; i < 8; i++) {
            int lin = tid + i * 256;
            int row = lin >> 4;
            int kq  = lin & 15;
            int grow = rowbase + row;
            float4 f = make_float4(0.f, 0.f, 0.f, 0.f);
            if (grow < M) {
                int k0 = kb + kq * 4;
                f = *(const float4*)(g_out1 + (size_t)grow * 128 + k0);
                f.x = fmaxf(f.x + __ldg(b1 + k0 + 0), 0.f);
                f.y = fmaxf(f.y + __ldg(b1 + k0 + 1), 0.f);
                f.z = fmaxf(f.z + __ldg(b1 + k0 + 2), 0.f);
                f.w = fmaxf(f.w + __ldg(b1 + k0 + 3), 0.f);
            }
            uint32_t h0, l0, h1, l1;
            split_pair(f.x, f.y, h0, l0);
            split_pair(f.z, f.w, h1, l1);
            int w = row * SA + kq * 2;
            As_hi[w] = h0; As_hi[w + 1] = h1;
            As_lo[w] = l0; As_lo[w + 1] = l1;
        }
#pragma unroll
        for (int i = 0; i < 2; i++) {
            int lin = tid + i * 256;
            int n = lin >> 3;
            int q = lin & 7;
            uint4 vh = *(const uint4*)(g_w2t_hi + (size_t)n * 128 + kb + q * 8);
            uint4 vl = *(const uint4*)(g_w2t_lo + (size_t)n * 128 + kb + q * 8);
            *(uint4*)&Bs_hi[n * SA + q * 4] = vh;
            *(uint4*)&Bs_lo[n * SA + q * 4] = vl;
        }
        __syncthreads();

#pragma unroll
        for (int ks = 0; ks < 4; ks++) {
            const uint32_t ko = ks * 32;
            uint32_t ah0, ah1, ah2, ah3, al0, al1, al2, al3;
            ldsm4(ah0, ah1, ah2, ah3, a_hi_base + ko);
            ldsm4(al0, al1, al2, al3, a_lo_base + ko);
#pragma unroll
            for (int p = 0; p < 4; p++) {
                uint32_t bh0, bh1, bh2, bh3, bl0, bl1, bl2, bl3;
                ldsm4(bh0, bh1, bh2, bh3, b_hi_base + p * 2304u + ko);
                ldsm4(bl0, bl1, bl2, bl3, b_lo_base + p * 2304u + ko);
                MMA_BF16(c[2 * p],     ah0, ah1, ah2, ah3, bh0, bh1);
                MMA_BF16(c[2 * p],     ah0, ah1, ah2, ah3, bl0, bl1);
                MMA_BF16(c[2 * p],     al0, al1, al2, al3, bh0, bh1);
                MMA_BF16(c[2 * p + 1], ah0, ah1, ah2, ah3, bh2, bh3);
                MMA_BF16(c[2 * p + 1], ah0, ah1, ah2, ah3, bl2, bl3);
                MMA_BF16(c[2 * p + 1], al0, al1, al2, al3, bh2, bh3);
            }
        }
        __syncthreads();
    }

    int row0 = rowbase + wrow + g;
    int row1 = row0 + 8;
#pragma unroll
    for (int nt = 0; nt < 8; nt++) {
        int n = nt * 8 + 2 * t;
        if (row0 < M) {
            __half2 v = __floats2half2_rn(c[nt][0], c[nt][1]);
            *(__half2*)(g_t16 + (size_t)row0 * 64 + n) = v;
        }
        if (row1 < M) {
            __half2 v = __floats2half2_rn(c[nt][2], c[nt][3]);
            *(__half2*)(g_t16 + (size_t)row1 * 64 + n) = v;
        }
    }
}

// ---- agg layer 2: out[c] = b2 + sum nm*t16[src] + dinv^2*t16[c] ------------
__global__ __launch_bounds__(256) void k_agg2(const float* __restrict__ b2,
                                              float* __restrict__ out, int n) {
    int c = blockIdx.x * 8 + (threadIdx.x >> 5);
    if (c >= n) return;
    int lane = threadIdx.x & 31;
    int beg = g_ptr[c], end = g_ptr[c + 1];

    float sc = g_dinv[c]; sc = sc * sc;
    __half2 hv = *(const __half2*)(g_t16 + (size_t)c * 64 + lane * 2);
    float2 self = __half22float2(hv);
    float2 acc = make_float2(__ldg(b2 + lane * 2)     + self.x * sc,
                             __ldg(b2 + lane * 2 + 1) + self.y * sc);

    for (int e = beg; e < end; e++) {
        int2  en = g_srt[e];
        float nm = __int_as_float(en.y);
        __half2 v = *(const __half2*)(g_t16 + (size_t)en.x * 64 + lane * 2);
        float2 f = __half22float2(v);
        acc.x = fmaf(f.x, nm, acc.x);
        acc.y = fmaf(f.y, nm, acc.y);
    }
    *(float2*)(out + (size_t)c * 64 + lane * 2) = acc;
}

// ---------------- entry ----------------------------------------------------
extern "C" void kernel_launch(void* const* d_in, const int* in_sizes, int n_in,
                              void* d_out, int out_size) {
    const float* x  = (const float*)d_in[0];
    const void*  ei = d_in[1];
    const float* ew = (const float*)d_in[2];
    const float* W1 = (const float*)d_in[3];
    const float* b1 = (const float*)d_in[4];
    const float* W2 = (const float*)d_in[5];
    const float* b2 = (const float*)d_in[6];
    float* out = (float*)d_out;

    int N = in_sizes[0] / F_IN;     // 50000
    int E = in_sizes[2];            // 800000
    int nScanBlocks = (N + 1023) / 1024;
    int nTiles = (N + 127) / 128;
    const int G1_SMEM = 18432 * 4;  // 73728 B
    const int G2_SMEM = 13824 * 4;  // 55296 B
    const int PREP_T = 128 * 128 + 128 * 64;   // 24576 threads for W split

    cudaFuncSetAttribute(k_gemm1, cudaFuncAttributeMaxDynamicSharedMemorySize,
                         G1_SMEM);
    cudaFuncSetAttribute(k_gemm2, cudaFuncAttributeMaxDynamicSharedMemorySize,
                         G2_SMEM);

    k_prep0   <<<(PREP_T + 255) / 256, 256>>>((const int*)ei, W1, W2);  // 0
    k_deg_hist<<<(E + 255) / 256, 256>>>(ei, ew, E);                    // 1
    k_dinv    <<<(N + 255) / 256, 256>>>(N);                            // 2
    k_gemm1   <<<nTiles, 256, G1_SMEM>>>(x, N);                         // 3 (profiled)
    k_scanA   <<<nScanBlocks, 1024>>>(N);                               // 4
    k_scanB   <<<1, 64>>>(nScanBlocks);                                 // 5
    k_scanC   <<<(N + 255) / 256, 256>>>(N);                            // 6
    k_place   <<<(E + 255) / 256, 256>>>(ei, ew, E);                    // 7
    k_agg1    <<<(N + 7) / 8, 256>>>(N);                                // 8
    k_gemm2   <<<nTiles, 256, G2_SMEM>>>(b1, N);                        // 9
    k_agg2    <<<(N + 7) / 8, 256>>>(b2, out, N);                       // 10
}

// round 9
// speedup vs baseline: 3.8459x; 1.2503x over previous
#include <cuda_runtime.h>
#include <cuda_fp16.h>
#include <cstdint>

#define N_NODES_MAX 50000
#define E_MAX       800000
#define F_IN  128
#define F_HID 128
#define F_OUT 64

// ---------------- scratch (device globals; no allocation allowed) ----------
__device__ float g_deg  [N_NODES_MAX];                 // zeroed after use (scanA)
__device__ float g_dinv [N_NODES_MAX];
__device__ int   g_cnt  [N_NODES_MAX];                 // zeroed after use (scanBC)
__device__ int   g_ptr  [N_NODES_MAX + 1];
__device__ int   g_cur  [N_NODES_MAX];
__device__ int   g_bsum [64];
__device__ int2  g_srt  [E_MAX];                       // (row, norm-as-int)
__device__ __align__(16) __half g_h16[(size_t)N_NODES_MAX * F_IN];  // x@W1
__device__ __align__(16) __half g_y16[(size_t)N_NODES_MAX * F_HID]; // relu(agg1+b1)
__device__ __align__(16) __half g_t16[(size_t)N_NODES_MAX * F_OUT]; // y16@W2
// pre-converted weights, transposed [n][k], fp16
__device__ __align__(16) __half g_w1t[128 * 128];
__device__ __align__(16) __half g_w2t[64 * 128];

// ---------------- helpers --------------------------------------------------
__device__ __forceinline__ int edge_idx(const void* ei, int is64, size_t pos) {
    if (is64) return (int)((const long long*)ei)[pos];
    return ((const int*)ei)[pos];
}

// per-block int64-vs-int32 detection (odd 32-bit words of first 64 values all
// zero <=> little-endian int64 with values < 2^31)
__device__ __forceinline__ int detect_is64_block(const int* ei32) {
    __shared__ int s_is64;
    if (threadIdx.x < 32) {
        int v = ei32[threadIdx.x * 2 + 1] | ei32[64 + threadIdx.x * 2 + 1];
        unsigned m = __ballot_sync(0xffffffffu, v != 0);
        if (threadIdx.x == 0) s_is64 = (m == 0u);
    }
    __syncthreads();
    return s_is64;
}

__device__ __forceinline__ uint32_t smem_u32(const void* p) {
    uint32_t a;
    asm("{ .reg .u64 t; cvta.to.shared.u64 t, %1; cvt.u32.u64 %0, t; }"
        : "=r"(a) : "l"(p));
    return a;
}

#define MMA_F16(c, a0, a1, a2, a3, b0, b1)                                     \
    asm volatile("mma.sync.aligned.m16n8k16.row.col.f32.f16.f16.f32 "          \
                 "{%0,%1,%2,%3}, {%4,%5,%6,%7}, {%8,%9}, {%0,%1,%2,%3};"       \
                 : "+f"((c)[0]), "+f"((c)[1]), "+f"((c)[2]), "+f"((c)[3])      \
                 : "r"(a0), "r"(a1), "r"(a2), "r"(a3), "r"(b0), "r"(b1))

__device__ __forceinline__ void ldsm4(uint32_t& r0, uint32_t& r1,
                                      uint32_t& r2, uint32_t& r3,
                                      uint32_t addr) {
    asm volatile("ldmatrix.sync.aligned.m8n8.x4.shared.b16 {%0,%1,%2,%3}, [%4];"
                 : "=r"(r0), "=r"(r1), "=r"(r2), "=r"(r3) : "r"(addr));
}

// ---------------- hist: deg/cnt accumulate + W fp16 convert ----------------
// blocks [0, EB): edge histogram; blocks [EB, ...): weight conversion
__global__ void k_hist(const void* __restrict__ ei,
                       const float* __restrict__ ew,
                       const float* __restrict__ W1,
                       const float* __restrict__ W2, int e, int EB) {
    if ((int)blockIdx.x < EB) {
        int is64 = detect_is64_block((const int*)ei);
        int i = blockIdx.x * blockDim.x + threadIdx.x;
        if (i < e) {
            int c = edge_idx(ei, is64, (size_t)e + i);
            atomicAdd(&g_deg[c], ew[i]);
            atomicAdd(&g_cnt[c], 1);
        }
    } else {
        int j = (blockIdx.x - EB) * blockDim.x + threadIdx.x;
        if (j < 128 * 128) {                   // W1 -> [n][k] fp16
            int k = j >> 7, n = j & 127;
            g_w1t[n * 128 + k] = __float2half(W1[j]);
        } else if (j < 128 * 128 + 128 * 64) { // W2 -> [n][k] fp16
            int r = j - 128 * 128;
            int k = r >> 6, n = r & 63;
            g_w2t[n * 128 + k] = __float2half(W2[r]);
        }
    }
}

// ---------------- scanA + dinv ---------------------------------------------
__global__ __launch_bounds__(1024) void k_scanA(int n) {
    __shared__ int s[1024];
    int i = blockIdx.x * 1024 + threadIdx.x;
    int v = (i < n) ? g_cnt[i] : 0;
    s[threadIdx.x] = v;
    __syncthreads();
#pragma unroll
    for (int off = 1; off < 1024; off <<= 1) {
        int t = (threadIdx.x >= off) ? s[threadIdx.x - off] : 0;
        __syncthreads();
        s[threadIdx.x] += t;
        __syncthreads();
    }
    if (i < n) {
        g_ptr[i] = s[threadIdx.x];             // inclusive
        float d = g_deg[i] + 1.0f;             // + self loop
        g_dinv[i] = rsqrtf(d);
        g_deg[i] = 0.f;                        // reset for replay
    }
    if (threadIdx.x == 1023) g_bsum[blockIdx.x] = s[1023];
}

// ---------------- scanBC: block-sum scan (redundant per block) + finalize ---
__global__ void k_scanBC(int n, int nb) {
    __shared__ int sb[64];
    int v0 = 0;
    if (threadIdx.x < 64) {
        v0 = (threadIdx.x < nb) ? g_bsum[threadIdx.x] : 0;
        sb[threadIdx.x] = v0;
    }
    __syncthreads();
#pragma unroll
    for (int off = 1; off < 64; off <<= 1) {
        int t = (threadIdx.x >= off && threadIdx.x < 64) ? sb[threadIdx.x - off] : 0;
        __syncthreads();
        if (threadIdx.x < 64) sb[threadIdx.x] += t;
        __syncthreads();
    }
    if (threadIdx.x < 64) sb[threadIdx.x] -= v0;   // exclusive
    __syncthreads();

    int i = blockIdx.x * blockDim.x + threadIdx.x;
    if (i < n) {
        int cnt = g_cnt[i];
        int excl = g_ptr[i] - cnt + sb[i >> 10];
        g_ptr[i] = excl;
        g_cur[i] = excl;
        g_cnt[i] = 0;                          // reset for replay
        if (i == n - 1) g_ptr[n] = excl + cnt;
    }
}

// ---------------- place edges into CSR -------------------------------------
__global__ void k_place(const void* __restrict__ ei,
                        const float* __restrict__ ew, int e) {
    int is64 = detect_is64_block((const int*)ei);
    int i = blockIdx.x * blockDim.x + threadIdx.x;
    if (i < e) {
        int r = edge_idx(ei, is64, (size_t)i);
        int c = edge_idx(ei, is64, (size_t)e + i);
        float nm = g_dinv[r] * ew[i] * g_dinv[c];
        int pos = atomicAdd(&g_cur[c], 1);
        g_srt[pos] = make_int2(r, __float_as_int(nm));
    }
}

// smem row stride: 36 u32 (144 B) -> conflict-free for LDSM and staging
#define SA 36

// ======== GEMM1 (fp16 mma + ldmatrix): g_h16 = fp16(x @ W1) ================
// block 256 thr (8 warps), tile 128x128, K chunked 2x64.
__global__ __launch_bounds__(256) void k_gemm1(const float* __restrict__ x,
                                               int M) {
    __shared__ uint32_t As[128 * SA];
    __shared__ uint32_t Bs[128 * SA];

    const int tid  = threadIdx.x;
    const int wid  = tid >> 5;
    const int lane = tid & 31;
    const int g    = lane >> 2;
    const int t    = lane & 3;
    const int rowbase = blockIdx.x * 128;
    const int wrow = wid * 16;

    const int lr = lane & 7, lm = lane >> 3;
    const uint32_t a_base = smem_u32(As) +
        (uint32_t)(wrow + lr + ((lm & 1) << 3)) * 144 + ((lm >> 1) << 4);
    const uint32_t b_base = smem_u32(Bs) +
        (uint32_t)(lr + ((lm >> 1) << 3)) * 144 + ((lm & 1) << 4);

    float c[16][4];
#pragma unroll
    for (int nt = 0; nt < 16; nt++)
#pragma unroll
        for (int j = 0; j < 4; j++) c[nt][j] = 0.f;

    for (int ch = 0; ch < 2; ch++) {
        const int kb = ch * 64;
        // --- stage A: fp32 -> fp16 pairs ---
#pragma unroll
        for (int i = 0; i < 8; i++) {
            int lin = tid + i * 256;           // 2048 float4
            int row = lin >> 4;
            int kq  = lin & 15;
            int grow = rowbase + row;
            float4 f = make_float4(0.f, 0.f, 0.f, 0.f);
            if (grow < M)
                f = *(const float4*)(x + (size_t)grow * 128 + kb + kq * 4);
            __half2 p0 = __floats2half2_rn(f.x, f.y);
            __half2 p1 = __floats2half2_rn(f.z, f.w);
            int w = row * SA + kq * 2;
            As[w]     = *reinterpret_cast<uint32_t*>(&p0);
            As[w + 1] = *reinterpret_cast<uint32_t*>(&p1);
        }
        // --- stage B: pure uint4 copies of pre-converted fp16 W1t ---
#pragma unroll
        for (int i = 0; i < 4; i++) {
            int lin = tid + i * 256;           // 1024 uint4
            int n = lin >> 3;
            int q = lin & 7;
            uint4 v = *(const uint4*)(g_w1t + (size_t)n * 128 + kb + q * 8);
            *(uint4*)&Bs[n * SA + q * 4] = v;
        }
        __syncthreads();

#pragma unroll
        for (int ks = 0; ks < 4; ks++) {
            const uint32_t ko = ks * 32;       // 16 fp16 = 32 B
            uint32_t a0, a1, a2, a3;
            ldsm4(a0, a1, a2, a3, a_base + ko);
#pragma unroll
            for (int p = 0; p < 8; p++) {
                uint32_t b0, b1, b2, b3;
                ldsm4(b0, b1, b2, b3, b_base + p * 2304u + ko);
                MMA_F16(c[2 * p],     a0, a1, a2, a3, b0, b1);
                MMA_F16(c[2 * p + 1], a0, a1, a2, a3, b2, b3);
            }
        }
        __syncthreads();
    }

    int row0 = rowbase + wrow + g;
    int row1 = row0 + 8;
#pragma unroll
    for (int nt = 0; nt < 16; nt++) {
        int n = nt * 8 + 2 * t;
        if (row0 < M) {
            __half2 v = __floats2half2_rn(c[nt][0], c[nt][1]);
            *(__half2*)(g_h16 + (size_t)row0 * 128 + n) = v;
        }
        if (row1 < M) {
            __half2 v = __floats2half2_rn(c[nt][2], c[nt][3]);
            *(__half2*)(g_h16 + (size_t)row1 * 128 + n) = v;
        }
    }
}

// ---- agg1: y16[c] = fp16(relu(b1 + dinv^2*h16[c] + sum nm*h16[src])) -------
__global__ __launch_bounds__(256) void k_agg1(const float* __restrict__ b1,
                                              int n) {
    int c = blockIdx.x * 8 + (threadIdx.x >> 5);
    if (c >= n) return;
    int lane = threadIdx.x & 31;
    int beg = g_ptr[c], end = g_ptr[c + 1];

    float sc = g_dinv[c]; sc = sc * sc;
    uint2 hv = *(const uint2*)(g_h16 + (size_t)c * 128 + lane * 4);
    float2 s0 = __half22float2(*(__half2*)&hv.x);
    float2 s1 = __half22float2(*(__half2*)&hv.y);
    float4 acc = make_float4(s0.x * sc, s0.y * sc, s1.x * sc, s1.y * sc);

    for (int e = beg; e < end; e++) {
        int2  en = g_srt[e];
        float nm = __int_as_float(en.y);
        uint2 v = *(const uint2*)(g_h16 + (size_t)en.x * 128 + lane * 4);
        float2 f0 = __half22float2(*(__half2*)&v.x);
        float2 f1 = __half22float2(*(__half2*)&v.y);
        acc.x = fmaf(f0.x, nm, acc.x);
        acc.y = fmaf(f0.y, nm, acc.y);
        acc.z = fmaf(f1.x, nm, acc.z);
        acc.w = fmaf(f1.y, nm, acc.w);
    }
    float4 bv = *(const float4*)(b1 + lane * 4);
    __half2 o0 = __floats2half2_rn(fmaxf(acc.x + bv.x, 0.f),
                                   fmaxf(acc.y + bv.y, 0.f));
    __half2 o1 = __floats2half2_rn(fmaxf(acc.z + bv.z, 0.f),
                                   fmaxf(acc.w + bv.w, 0.f));
    uint2 ov = make_uint2(*reinterpret_cast<uint32_t*>(&o0),
                          *reinterpret_cast<uint32_t*>(&o1));
    *(uint2*)(g_y16 + (size_t)c * 128 + lane * 4) = ov;
}

// ======== GEMM2 (fp16 mma + ldmatrix): g_t16 = fp16(y16 @ W2) ==============
// block 256 thr, tile 128x64, K chunked 2x64. A-stage = pure copies.
__global__ __launch_bounds__(256) void k_gemm2(int M) {
    __shared__ uint32_t As[128 * SA];
    __shared__ uint32_t Bs[64 * SA];

    const int tid  = threadIdx.x;
    const int wid  = tid >> 5;
    const int lane = tid & 31;
    const int g    = lane >> 2;
    const int t    = lane & 3;
    const int rowbase = blockIdx.x * 128;
    const int wrow = wid * 16;

    const int lr = lane & 7, lm = lane >> 3;
    const uint32_t a_base = smem_u32(As) +
        (uint32_t)(wrow + lr + ((lm & 1) << 3)) * 144 + ((lm >> 1) << 4);
    const uint32_t b_base = smem_u32(Bs) +
        (uint32_t)(lr + ((lm >> 1) << 3)) * 144 + ((lm & 1) << 4);

    float c[8][4];
#pragma unroll
    for (int nt = 0; nt < 8; nt++)
#pragma unroll
        for (int j = 0; j < 4; j++) c[nt][j] = 0.f;

    for (int ch = 0; ch < 2; ch++) {
        const int kb = ch * 64;
        // --- stage A: direct fp16 copies from y16 ---
#pragma unroll
        for (int i = 0; i < 4; i++) {
            int lin = tid + i * 256;           // 1024 uint4
            int row = lin >> 3;
            int q   = lin & 7;
            int grow = rowbase + row;
            uint4 v = make_uint4(0u, 0u, 0u, 0u);
            if (grow < M)
                v = *(const uint4*)(g_y16 + (size_t)grow * 128 + kb + q * 8);
            *(uint4*)&As[row * SA + q * 4] = v;
        }
        // --- stage B: copies of pre-converted fp16 W2t ---
#pragma unroll
        for (int i = 0; i < 2; i++) {
            int lin = tid + i * 256;           // 512 uint4
            int n = lin >> 3;
            int q = lin & 7;
            uint4 v = *(const uint4*)(g_w2t + (size_t)n * 128 + kb + q * 8);
            *(uint4*)&Bs[n * SA + q * 4] = v;
        }
        __syncthreads();

#pragma unroll
        for (int ks = 0; ks < 4; ks++) {
            const uint32_t ko = ks * 32;
            uint32_t a0, a1, a2, a3;
            ldsm4(a0, a1, a2, a3, a_base + ko);
#pragma unroll
            for (int p = 0; p < 4; p++) {
                uint32_t b0, b1, b2, b3;
                ldsm4(b0, b1, b2, b3, b_base + p * 2304u + ko);
                MMA_F16(c[2 * p],     a0, a1, a2, a3, b0, b1);
                MMA_F16(c[2 * p + 1], a0, a1, a2, a3, b2, b3);
            }
        }
        __syncthreads();
    }

    int row0 = rowbase + wrow + g;
    int row1 = row0 + 8;
#pragma unroll
    for (int nt = 0; nt < 8; nt++) {
        int n = nt * 8 + 2 * t;
        if (row0 < M) {
            __half2 v = __floats2half2_rn(c[nt][0], c[nt][1]);
            *(__half2*)(g_t16 + (size_t)row0 * 64 + n) = v;
        }
        if (row1 < M) {
            __half2 v = __floats2half2_rn(c[nt][2], c[nt][3]);
            *(__half2*)(g_t16 + (size_t)row1 * 64 + n) = v;
        }
    }
}

// ---- agg2: out[c] = b2 + dinv^2*t16[c] + sum nm*t16[src] -------------------
__global__ __launch_bounds__(256) void k_agg2(const float* __restrict__ b2,
                                              float* __restrict__ out, int n) {
    int c = blockIdx.x * 8 + (threadIdx.x >> 5);
    if (c >= n) return;
    int lane = threadIdx.x & 31;
    int beg = g_ptr[c], end = g_ptr[c + 1];

    float sc = g_dinv[c]; sc = sc * sc;
    __half2 hv = *(const __half2*)(g_t16 + (size_t)c * 64 + lane * 2);
    float2 self = __half22float2(hv);
    float2 acc = make_float2(__ldg(b2 + lane * 2)     + self.x * sc,
                             __ldg(b2 + lane * 2 + 1) + self.y * sc);

    for (int e = beg; e < end; e++) {
        int2  en = g_srt[e];
        float nm = __int_as_float(en.y);
        __half2 v = *(const __half2*)(g_t16 + (size_t)en.x * 64 + lane * 2);
        float2 f = __half22float2(v);
        acc.x = fmaf(f.x, nm, acc.x);
        acc.y = fmaf(f.y, nm, acc.y);
    }
    *(float2*)(out + (size_t)c * 64 + lane * 2) = acc;
}

// ---------------- entry ----------------------------------------------------
extern "C" void kernel_launch(void* const* d_in, const int* in_sizes, int n_in,
                              void* d_out, int out_size) {
    const float* x  = (const float*)d_in[0];
    const void*  ei = d_in[1];
    const float* ew = (const float*)d_in[2];
    const float* W1 = (const float*)d_in[3];
    const float* b1 = (const float*)d_in[4];
    const float* W2 = (const float*)d_in[5];
    const float* b2 = (const float*)d_in[6];
    float* out = (float*)d_out;

    int N = in_sizes[0] / F_IN;     // 50000
    int E = in_sizes[2];            // 800000
    int nScanBlocks = (N + 1023) / 1024;          // 49
    int nTiles = (N + 127) / 128;                 // 391
    int EB = (E + 255) / 256;                     // edge blocks in k_hist
    int WB = (128 * 128 + 128 * 64 + 255) / 256;  // weight-convert blocks

    k_hist  <<<EB + WB, 256>>>(ei, ew, W1, W2, E, EB);      // 0
    k_scanA <<<nScanBlocks, 1024>>>(N);                     // 1
    k_scanBC<<<(N + 255) / 256, 256>>>(N, nScanBlocks);     // 2
    k_gemm1 <<<nTiles, 256>>>(x, N);                        // 3 (profiled)
    k_place <<<EB, 256>>>(ei, ew, E);                       // 4
    k_agg1  <<<(N + 7) / 8, 256>>>(b1, N);                  // 5
    k_gemm2 <<<nTiles, 256>>>(N);                           // 6
    k_agg2  <<<(N + 7) / 8, 256>>>(b2, out, N);             // 7
}